// round 5
// baseline (speedup 1.0000x reference)
#include <cuda_runtime.h>

#define D_MODEL 1024
#define NHEAD   16
#define HD      64
#define SEQ     2048
#define BATCH   2
#define M_TOT   (BATCH * SEQ)   // 4096
#define QKV_W   (3 * D_MODEL)   // 3072

// Scratch (no cudaMalloc allowed). All hold tf32 bit patterns.
__device__ unsigned g_qkv[(size_t)M_TOT * QKV_W];
__device__ unsigned g_ao [(size_t)M_TOT * D_MODEL];
__device__ unsigned g_xc [(size_t)M_TOT * D_MODEL];
__device__ unsigned g_wq [(size_t)QKV_W * D_MODEL];
__device__ unsigned g_wo [(size_t)D_MODEL * D_MODEL];

__device__ __forceinline__ unsigned f2tf(float f) {
    unsigned u;
    asm("cvt.rna.tf32.f32 %0, %1;" : "=r"(u) : "f"(f));
    return u;
}

__device__ __forceinline__ void mma_tf32(float* c, const unsigned* a,
                                         unsigned b0, unsigned b1) {
    asm volatile(
        "mma.sync.aligned.m16n8k8.row.col.f32.tf32.tf32.f32 "
        "{%0,%1,%2,%3},{%4,%5,%6,%7},{%8,%9},{%0,%1,%2,%3};\n"
        : "+f"(c[0]), "+f"(c[1]), "+f"(c[2]), "+f"(c[3])
        : "r"(a[0]), "r"(a[1]), "r"(a[2]), "r"(a[3]), "r"(b0), "r"(b1));
}

__device__ __forceinline__ void cp_async16(void* smem_dst, const void* gmem_src) {
    unsigned s = (unsigned)__cvta_generic_to_shared(smem_dst);
    asm volatile("cp.async.cg.shared.global [%0], [%1], 16;\n" :: "r"(s), "l"(gmem_src));
}
#define CP_COMMIT() asm volatile("cp.async.commit_group;\n" ::: "memory")
#define CP_WAIT1()  asm volatile("cp.async.wait_group 1;\n" ::: "memory")
#define CP_WAIT0()  asm volatile("cp.async.wait_group 0;\n" ::: "memory")

// ---------------------------------------------------------------------------
// fp32 -> tf32 pre-pass
// ---------------------------------------------------------------------------
#define XC_F4 ((M_TOT * D_MODEL) / 4)
#define WQ_F4 ((QKV_W * D_MODEL) / 4)
#define WO_F4 ((D_MODEL * D_MODEL) / 4)
#define CONV_BLOCKS ((XC_F4 + WQ_F4 + WO_F4) / 256)

__global__ void conv_tf32(const float4* __restrict__ x,
                          const float4* __restrict__ wq,
                          const float4* __restrict__ wo,
                          uint4* __restrict__ ox,
                          uint4* __restrict__ owq,
                          uint4* __restrict__ owo) {
    const int idx = blockIdx.x * 256 + threadIdx.x;
    const float4* src;
    uint4* dst;
    int i;
    if (idx < XC_F4)                { src = x;  dst = ox;  i = idx; }
    else if (idx < XC_F4 + WQ_F4)   { src = wq; dst = owq; i = idx - XC_F4; }
    else                            { src = wo; dst = owo; i = idx - XC_F4 - WQ_F4; }
    float4 v = src[i];
    dst[i] = make_uint4(f2tf(v.x), f2tf(v.y), f2tf(v.z), f2tf(v.w));
}

// ---------------------------------------------------------------------------
// C[m][n] = sum_k A[m][k]*B[n][k], tf32 bits. 128x128 block tile, K-tile 32,
// 128 threads (4 warps, each 64x64), cp.async.cg double-buffered.
// ---------------------------------------------------------------------------
#define GSTR 36
#define GTILE (128 * GSTR)
#define SMEM_GEMM (4 * GTILE * 4)   // 73728 B

template <bool OUT_TF32>
__global__ __launch_bounds__(128)
void gemm_tt(const unsigned* __restrict__ A, const unsigned* __restrict__ B,
             void* __restrict__ Cv, int M, int N, int K) {
    extern __shared__ unsigned smg[];

    const int t    = threadIdx.x;
    const int lane = t & 31;
    const int w    = t >> 5;
    const int gid  = lane >> 2;
    const int tig  = lane & 3;
    const int wm   = w & 1;       // 64-row half
    const int wn   = w >> 1;      // 64-col half
    const int m0   = blockIdx.y * 128;
    const int n0   = blockIdx.x * 128;

    const int lr = t >> 3;        // 0..15 (row within 16-row pass)
    const int lc = (t & 7) * 4;   // 0..28

    float acc[4][8][4];
#pragma unroll
    for (int i = 0; i < 4; i++)
#pragma unroll
        for (int j = 0; j < 8; j++)
#pragma unroll
            for (int e = 0; e < 4; e++) acc[i][j][e] = 0.f;

    const unsigned* Ap = A + (size_t)(m0 + lr) * K + lc;
    const unsigned* Bp = B + (size_t)(n0 + lr) * K + lc;

    const int nkt = K / 32;

    {
        unsigned* as = smg + lr * GSTR + lc;
        unsigned* bs = smg + 2 * GTILE + lr * GSTR + lc;
#pragma unroll
        for (int p = 0; p < 8; p++) {
            cp_async16(as + p * 16 * GSTR, Ap + (size_t)(p * 16) * K);
            cp_async16(bs + p * 16 * GSTR, Bp + (size_t)(p * 16) * K);
        }
    }
    CP_COMMIT();

    for (int kt = 0; kt < nkt; kt++) {
        const int cur = kt & 1;
        if (kt + 1 < nkt) {
            const int nb = cur ^ 1;
            unsigned* as = smg + nb * GTILE + lr * GSTR + lc;
            unsigned* bs = smg + 2 * GTILE + nb * GTILE + lr * GSTR + lc;
            const unsigned* Ap2 = Ap + (kt + 1) * 32;
            const unsigned* Bp2 = Bp + (kt + 1) * 32;
#pragma unroll
            for (int p = 0; p < 8; p++) {
                cp_async16(as + p * 16 * GSTR, Ap2 + (size_t)(p * 16) * K);
                cp_async16(bs + p * 16 * GSTR, Bp2 + (size_t)(p * 16) * K);
            }
        }
        CP_COMMIT();
        CP_WAIT1();
        __syncthreads();

        const unsigned* As = smg + cur * GTILE;
        const unsigned* Bs = smg + 2 * GTILE + cur * GTILE;
        const int am = wm * 64;
        const int bn = wn * 64;
#pragma unroll
        for (int s = 0; s < 4; s++) {
            const int kk = s * 8;
            unsigned av[4][4];
#pragma unroll
            for (int mi = 0; mi < 4; mi++) {
                const int r  = (am + 16 * mi + gid) * GSTR;
                const int r8 = r + 8 * GSTR;
                av[mi][0] = As[r + kk + tig];
                av[mi][1] = As[r8 + kk + tig];
                av[mi][2] = As[r + kk + tig + 4];
                av[mi][3] = As[r8 + kk + tig + 4];
            }
            unsigned bv[8][2];
#pragma unroll
            for (int nj = 0; nj < 8; nj++) {
                const int r = (bn + 8 * nj + gid) * GSTR;
                bv[nj][0] = Bs[r + kk + tig];
                bv[nj][1] = Bs[r + kk + tig + 4];
            }
#pragma unroll
            for (int mi = 0; mi < 4; mi++)
#pragma unroll
                for (int nj = 0; nj < 8; nj++)
                    mma_tf32(acc[mi][nj], av[mi], bv[nj][0], bv[nj][1]);
        }
        __syncthreads();
    }

    // epilogue
#pragma unroll
    for (int mi = 0; mi < 4; mi++) {
        const int r = m0 + wm * 64 + 16 * mi + gid;
#pragma unroll
        for (int nj = 0; nj < 8; nj++) {
            const int c = n0 + wn * 64 + 8 * nj + 2 * tig;
            if (OUT_TF32) {
                unsigned* C = (unsigned*)Cv;
                *(uint2*)(C + (size_t)r * N + c) =
                    make_uint2(f2tf(acc[mi][nj][0]), f2tf(acc[mi][nj][1]));
                *(uint2*)(C + (size_t)(r + 8) * N + c) =
                    make_uint2(f2tf(acc[mi][nj][2]), f2tf(acc[mi][nj][3]));
            } else {
                float* C = (float*)Cv;
                *(float2*)(C + (size_t)r * N + c) =
                    make_float2(acc[mi][nj][0], acc[mi][nj][1]);
                *(float2*)(C + (size_t)(r + 8) * N + c) =
                    make_float2(acc[mi][nj][2], acc[mi][nj][3]);
            }
        }
    }
}

// ---------------------------------------------------------------------------
// Causal flash attention, tf32, 128-query tiles, 8 warps (256 threads),
// cp.async.cg double-buffered K/V. 2 blocks/SM -> 16 warps.
// ---------------------------------------------------------------------------
#define KS_STRIDE 68
#define VS_STRIDE 72
#define PS_STRIDE 68
#define KS_ELEMS (64 * KS_STRIDE)
#define VS_ELEMS (64 * VS_STRIDE)
#define QROWS 128
#define SMEM_ATTN ((2 * KS_ELEMS + 2 * VS_ELEMS + QROWS * PS_STRIDE) * 4)  // 106496 B

__global__ __launch_bounds__(256)
void attn_tf32(const unsigned* __restrict__ qkv, unsigned* __restrict__ out) {
    extern __shared__ unsigned sma[];
    unsigned* KsF = sma;
    unsigned* VsF = sma + 2 * KS_ELEMS;
    unsigned* Ps  = sma + 2 * KS_ELEMS + 2 * VS_ELEMS;

    const int qt   = gridDim.x - 1 - blockIdx.x;   // heavy tiles first
    const int h    = blockIdx.y;
    const int b    = blockIdx.z;
    const int t    = threadIdx.x;
    const int lane = t & 31;
    const int w    = t >> 5;        // 0..7
    const int gid  = lane >> 2;
    const int tig  = lane & 3;
    const int q0   = qt * QROWS;

    const int lrow = t >> 4;        // 0..15
    const int lc4  = (t & 15) * 4;  // 0..60

    const unsigned* kbase = qkv + (size_t)b * SEQ * QKV_W + D_MODEL + h * HD;
    const unsigned* vbase = kbase + D_MODEL;

    // prologue: Q tile (128 rows) + K/V tile 0
    {
        const unsigned* qp = qkv + (size_t)(b * SEQ + q0) * QKV_W + h * HD;
#pragma unroll
        for (int p = 0; p < 8; p++) {
            const int row = p * 16 + lrow;
            cp_async16(&Ps[row * PS_STRIDE + lc4], qp + (size_t)row * QKV_W + lc4);
        }
#pragma unroll
        for (int p = 0; p < 4; p++) {
            const int row = p * 16 + lrow;
            cp_async16(&KsF[row * KS_STRIDE + lc4], kbase + (size_t)row * QKV_W + lc4);
            cp_async16(&VsF[row * VS_STRIDE + lc4], vbase + (size_t)row * QKV_W + lc4);
        }
    }
    CP_COMMIT();
    CP_WAIT0();
    __syncthreads();

    // Q fragments -> registers (scale by exact power of two)
    unsigned qf[8][4];
    {
        const int r0 = (16 * w + gid) * PS_STRIDE;
        const int r1 = (16 * w + gid + 8) * PS_STRIDE;
#pragma unroll
        for (int s = 0; s < 8; s++) {
            qf[s][0] = __float_as_uint(__uint_as_float(Ps[r0 + 8 * s + tig]) * 0.125f);
            qf[s][1] = __float_as_uint(__uint_as_float(Ps[r1 + 8 * s + tig]) * 0.125f);
            qf[s][2] = __float_as_uint(__uint_as_float(Ps[r0 + 8 * s + tig + 4]) * 0.125f);
            qf[s][3] = __float_as_uint(__uint_as_float(Ps[r1 + 8 * s + tig + 4]) * 0.125f);
        }
    }

    float o[8][4];
#pragma unroll
    for (int j = 0; j < 8; j++)
#pragma unroll
        for (int e = 0; e < 4; e++) o[j][e] = 0.f;
    float m0 = -1e30f, m1 = -1e30f, l0 = 0.f, l1 = 0.f;

    const int row0 = q0 + 16 * w + gid;
    const int jt_max = 2 * qt + 1;     // key tiles are 64 wide, q tile 128

    for (int jt = 0; jt <= jt_max; jt++) {
        const int cur = jt & 1;
        if (jt + 1 <= jt_max) {
            const int nb = cur ^ 1;
            const unsigned* kp = kbase + (size_t)(jt + 1) * 64 * QKV_W;
            const unsigned* vp = vbase + (size_t)(jt + 1) * 64 * QKV_W;
#pragma unroll
            for (int p = 0; p < 4; p++) {
                const int row = p * 16 + lrow;
                cp_async16(&KsF[nb * KS_ELEMS + row * KS_STRIDE + lc4],
                           kp + (size_t)row * QKV_W + lc4);
                cp_async16(&VsF[nb * VS_ELEMS + row * VS_STRIDE + lc4],
                           vp + (size_t)row * QKV_W + lc4);
            }
        }
        CP_COMMIT();
        CP_WAIT1();
        __syncthreads();

        const unsigned* Ks = KsF + cur * KS_ELEMS;
        const unsigned* Vs = VsF + cur * VS_ELEMS;
        const int k0 = jt * 64;

        // S = Q K^T
        float sacc[8][4];
#pragma unroll
        for (int j = 0; j < 8; j++)
#pragma unroll
            for (int e = 0; e < 4; e++) sacc[j][e] = 0.f;

#pragma unroll
        for (int s = 0; s < 8; s++) {
#pragma unroll
            for (int j = 0; j < 8; j++) {
                const int kr = (8 * j + gid) * KS_STRIDE + 8 * s + tig;
                mma_tf32(sacc[j], qf[s], Ks[kr], Ks[kr + 4]);
            }
        }

        // mask (only the last two tiles can cross the diagonal) + row max
        const bool need_mask = (jt >= 2 * qt);
        float mt0 = -1e30f, mt1 = -1e30f;
#pragma unroll
        for (int j = 0; j < 8; j++) {
            const int cb = k0 + 8 * j + 2 * tig;
            if (need_mask) {
                if (cb     > row0)     sacc[j][0] = -1e30f;
                if (cb + 1 > row0)     sacc[j][1] = -1e30f;
                if (cb     > row0 + 8) sacc[j][2] = -1e30f;
                if (cb + 1 > row0 + 8) sacc[j][3] = -1e30f;
            }
            mt0 = fmaxf(mt0, fmaxf(sacc[j][0], sacc[j][1]));
            mt1 = fmaxf(mt1, fmaxf(sacc[j][2], sacc[j][3]));
        }
        mt0 = fmaxf(mt0, __shfl_xor_sync(0xffffffffu, mt0, 1));
        mt0 = fmaxf(mt0, __shfl_xor_sync(0xffffffffu, mt0, 2));
        mt1 = fmaxf(mt1, __shfl_xor_sync(0xffffffffu, mt1, 1));
        mt1 = fmaxf(mt1, __shfl_xor_sync(0xffffffffu, mt1, 2));

        const float mn0 = fmaxf(m0, mt0);
        const float mn1 = fmaxf(m1, mt1);
        const float al0 = __expf(m0 - mn0);
        const float al1 = __expf(m1 - mn1);
        m0 = mn0; m1 = mn1;

        // P = exp(S - m) -> warp-private Ps rows (tf32), row sums
        float ls0 = 0.f, ls1 = 0.f;
        {
            const int pr0 = (16 * w + gid) * PS_STRIDE;
            const int pr1 = (16 * w + gid + 8) * PS_STRIDE;
#pragma unroll
            for (int j = 0; j < 8; j++) {
                const int c = 8 * j + 2 * tig;
                float p00 = __expf(sacc[j][0] - mn0);
                float p01 = __expf(sacc[j][1] - mn0);
                float p10 = __expf(sacc[j][2] - mn1);
                float p11 = __expf(sacc[j][3] - mn1);
                ls0 += p00 + p01;
                ls1 += p10 + p11;
                Ps[pr0 + c]     = f2tf(p00);
                Ps[pr0 + c + 1] = f2tf(p01);
                Ps[pr1 + c]     = f2tf(p10);
                Ps[pr1 + c + 1] = f2tf(p11);
            }
        }
        ls0 += __shfl_xor_sync(0xffffffffu, ls0, 1);
        ls0 += __shfl_xor_sync(0xffffffffu, ls0, 2);
        ls1 += __shfl_xor_sync(0xffffffffu, ls1, 1);
        ls1 += __shfl_xor_sync(0xffffffffu, ls1, 2);
        l0 = l0 * al0 + ls0;
        l1 = l1 * al1 + ls1;

#pragma unroll
        for (int j = 0; j < 8; j++) {
            o[j][0] *= al0; o[j][1] *= al0;
            o[j][2] *= al1; o[j][3] *= al1;
        }
        __syncwarp();

        // O += P V
#pragma unroll
        for (int s = 0; s < 8; s++) {
            unsigned pa[4];
            const int pr0 = (16 * w + gid) * PS_STRIDE + 8 * s;
            const int pr1 = (16 * w + gid + 8) * PS_STRIDE + 8 * s;
            pa[0] = Ps[pr0 + tig];
            pa[1] = Ps[pr1 + tig];
            pa[2] = Ps[pr0 + tig + 4];
            pa[3] = Ps[pr1 + tig + 4];
#pragma unroll
            for (int j = 0; j < 8; j++) {
                const int vb = (8 * s + tig) * VS_STRIDE + 8 * j + gid;
                mma_tf32(o[j], pa, Vs[vb], Vs[vb + 4 * VS_STRIDE]);
            }
        }
        __syncthreads();
    }

    // epilogue -> tf32 bits for the output projection
    const float i0 = 1.f / l0;
    const float i1 = 1.f / l1;
    unsigned* op0 = out + (size_t)(b * SEQ + row0) * D_MODEL + h * HD;
    unsigned* op1 = op0 + (size_t)8 * D_MODEL;
#pragma unroll
    for (int j = 0; j < 8; j++) {
        const int c = 8 * j + 2 * tig;
        *(uint2*)(op0 + c) = make_uint2(f2tf(o[j][0] * i0), f2tf(o[j][1] * i0));
        *(uint2*)(op1 + c) = make_uint2(f2tf(o[j][2] * i1), f2tf(o[j][3] * i1));
    }
}

extern "C" void kernel_launch(void* const* d_in, const int* in_sizes, int n_in,
                              void* d_out, int out_size) {
    const float* x     = (const float*)d_in[0];
    const float* w_qkv = (const float*)d_in[1];
    const float* w_o   = (const float*)d_in[2];
    float* out         = (float*)d_out;

    unsigned *qkv, *ao, *xc, *wq, *wo;
    cudaGetSymbolAddress((void**)&qkv, g_qkv);
    cudaGetSymbolAddress((void**)&ao,  g_ao);
    cudaGetSymbolAddress((void**)&xc,  g_xc);
    cudaGetSymbolAddress((void**)&wq,  g_wq);
    cudaGetSymbolAddress((void**)&wo,  g_wo);

    static bool attr_set = false;
    if (!attr_set) {
        cudaFuncSetAttribute(gemm_tt<true>,  cudaFuncAttributeMaxDynamicSharedMemorySize, SMEM_GEMM);
        cudaFuncSetAttribute(gemm_tt<false>, cudaFuncAttributeMaxDynamicSharedMemorySize, SMEM_GEMM);
        cudaFuncSetAttribute(attn_tf32, cudaFuncAttributeMaxDynamicSharedMemorySize, SMEM_ATTN);
        attr_set = true;
    }

    conv_tf32<<<CONV_BLOCKS, 256>>>((const float4*)x, (const float4*)w_qkv, (const float4*)w_o,
                                    (uint4*)xc, (uint4*)wq, (uint4*)wo);

    gemm_tt<true><<<dim3(QKV_W / 128, M_TOT / 128), 128, SMEM_GEMM>>>(xc, wq, qkv, M_TOT, QKV_W, D_MODEL);

    attn_tf32<<<dim3(SEQ / QROWS, NHEAD, BATCH), 256, SMEM_ATTN>>>(qkv, ao);

    gemm_tt<false><<<dim3(D_MODEL / 128, M_TOT / 128), 128, SMEM_GEMM>>>(ao, wo, out, M_TOT, D_MODEL, D_MODEL);
}

// round 6
// speedup vs baseline: 1.0741x; 1.0741x over previous
#include <cuda_runtime.h>

#define D_MODEL 1024
#define NHEAD   16
#define HD      64
#define SEQ     2048
#define BATCH   2
#define M_TOT   (BATCH * SEQ)   // 4096
#define QKV_W   (3 * D_MODEL)   // 3072

// Scratch (no cudaMalloc allowed). All hold tf32 bit patterns.
__device__ unsigned g_qkv[(size_t)M_TOT * QKV_W];
__device__ unsigned g_ao [(size_t)M_TOT * D_MODEL];
__device__ unsigned g_xc [(size_t)M_TOT * D_MODEL];
__device__ unsigned g_wq [(size_t)QKV_W * D_MODEL];
__device__ unsigned g_wo [(size_t)D_MODEL * D_MODEL];

__device__ __forceinline__ unsigned f2tf(float f) {
    unsigned u;
    asm("cvt.rna.tf32.f32 %0, %1;" : "=r"(u) : "f"(f));
    return u;
}

__device__ __forceinline__ void mma_tf32(float* c, const unsigned* a,
                                         unsigned b0, unsigned b1) {
    asm volatile(
        "mma.sync.aligned.m16n8k8.row.col.f32.tf32.tf32.f32 "
        "{%0,%1,%2,%3},{%4,%5,%6,%7},{%8,%9},{%0,%1,%2,%3};\n"
        : "+f"(c[0]), "+f"(c[1]), "+f"(c[2]), "+f"(c[3])
        : "r"(a[0]), "r"(a[1]), "r"(a[2]), "r"(a[3]), "r"(b0), "r"(b1));
}

__device__ __forceinline__ void cp_async16(void* smem_dst, const void* gmem_src) {
    unsigned s = (unsigned)__cvta_generic_to_shared(smem_dst);
    asm volatile("cp.async.cg.shared.global [%0], [%1], 16;\n" :: "r"(s), "l"(gmem_src));
}
#define CP_COMMIT() asm volatile("cp.async.commit_group;\n" ::: "memory")
#define CP_WAIT1()  asm volatile("cp.async.wait_group 1;\n" ::: "memory")
#define CP_WAIT0()  asm volatile("cp.async.wait_group 0;\n" ::: "memory")

// ---------------------------------------------------------------------------
// fp32 -> tf32 pre-pass
// ---------------------------------------------------------------------------
#define XC_F4 ((M_TOT * D_MODEL) / 4)
#define WQ_F4 ((QKV_W * D_MODEL) / 4)
#define WO_F4 ((D_MODEL * D_MODEL) / 4)
#define CONV_BLOCKS ((XC_F4 + WQ_F4 + WO_F4) / 256)

__global__ void conv_tf32(const float4* __restrict__ x,
                          const float4* __restrict__ wq,
                          const float4* __restrict__ wo,
                          uint4* __restrict__ ox,
                          uint4* __restrict__ owq,
                          uint4* __restrict__ owo) {
    const int idx = blockIdx.x * 256 + threadIdx.x;
    const float4* src;
    uint4* dst;
    int i;
    if (idx < XC_F4)                { src = x;  dst = ox;  i = idx; }
    else if (idx < XC_F4 + WQ_F4)   { src = wq; dst = owq; i = idx - XC_F4; }
    else                            { src = wo; dst = owo; i = idx - XC_F4 - WQ_F4; }
    float4 v = src[i];
    dst[i] = make_uint4(f2tf(v.x), f2tf(v.y), f2tf(v.z), f2tf(v.w));
}

// ---------------------------------------------------------------------------
// C[m][n] = sum_k A[m][k]*B[n][k], tf32 bits. 128x128 block tile, K-tile 32,
// 256 threads (8 warps, 64x32 warp tiles), 3-stage cp.async pipeline,
// XOR-swizzled smem (no padding), one __syncthreads per K-tile, 2 CTAs/SM.
// ---------------------------------------------------------------------------
#define NSTAGE 3
#define GTILE (128 * 32)
#define SMEM_GEMM (2 * NSTAGE * GTILE * 4)   // 98304 B

__device__ __forceinline__ int swz(int r, int c) {
    return r * 32 + (c ^ ((r & 7) << 2));
}

template <bool OUT_TF32>
__global__ __launch_bounds__(256, 2)
void gemm_tt(const unsigned* __restrict__ A, const unsigned* __restrict__ B,
             void* __restrict__ Cv, int M, int N, int K) {
    extern __shared__ unsigned smg[];
    unsigned* Abuf = smg;                    // [NSTAGE][128*32]
    unsigned* Bbuf = smg + NSTAGE * GTILE;   // [NSTAGE][128*32]

    const int t    = threadIdx.x;
    const int lane = t & 31;
    const int w    = t >> 5;
    const int gid  = lane >> 2;
    const int tig  = lane & 3;
    const int wm   = w & 1;       // 64-row half
    const int wn   = w >> 1;      // 32-col quarter
    const int m0   = blockIdx.y * 128;
    const int n0   = blockIdx.x * 128;

    const int lr = t >> 3;        // 0..31
    const int lc = (t & 7) * 4;   // 0,4,...,28

    float acc[4][4][4];
#pragma unroll
    for (int i = 0; i < 4; i++)
#pragma unroll
        for (int j = 0; j < 4; j++)
#pragma unroll
            for (int e = 0; e < 4; e++) acc[i][j][e] = 0.f;

    const unsigned* Ap = A + (size_t)(m0 + lr) * K + lc;
    const unsigned* Bp = B + (size_t)(n0 + lr) * K + lc;

    const int nkt = K / 32;

    // issue one K-tile into a stage
    auto issue = [&](int stage, int kt) {
        unsigned* as = Abuf + stage * GTILE;
        unsigned* bs = Bbuf + stage * GTILE;
        const unsigned* Ap2 = Ap + kt * 32;
        const unsigned* Bp2 = Bp + kt * 32;
#pragma unroll
        for (int p = 0; p < 4; p++) {
            const int row = p * 32 + lr;
            const int off = swz(row, lc);
            cp_async16(as + off, Ap2 + (size_t)(p * 32) * K);
            cp_async16(bs + off, Bp2 + (size_t)(p * 32) * K);
        }
    };

    // prologue: stages 0,1 in flight
    issue(0, 0); CP_COMMIT();
    issue(1, 1); CP_COMMIT();

    int stage = 0;
    for (int kt = 0; kt < nkt; kt++) {
        CP_WAIT1();          // tile kt's group complete (<=1 pending)
        __syncthreads();     // visible to all warps; stage (kt+2)%3 free

        if (kt + 2 < nkt) {
            int ns = stage + 2; if (ns >= NSTAGE) ns -= NSTAGE;
            issue(ns, kt + 2);
            CP_COMMIT();
        }

        const unsigned* As = Abuf + stage * GTILE;
        const unsigned* Bs = Bbuf + stage * GTILE;
        const int am = wm * 64;
        const int bn = wn * 32;
#pragma unroll
        for (int s = 0; s < 4; s++) {
            const int kk = s * 8;
            unsigned av[4][4];
#pragma unroll
            for (int mi = 0; mi < 4; mi++) {
                const int r  = am + 16 * mi + gid;
                const int r8 = r + 8;
                av[mi][0] = As[swz(r,  kk + tig)];
                av[mi][1] = As[swz(r8, kk + tig)];
                av[mi][2] = As[swz(r,  kk + tig + 4)];
                av[mi][3] = As[swz(r8, kk + tig + 4)];
            }
            unsigned bv[4][2];
#pragma unroll
            for (int nj = 0; nj < 4; nj++) {
                const int r = bn + 8 * nj + gid;
                bv[nj][0] = Bs[swz(r, kk + tig)];
                bv[nj][1] = Bs[swz(r, kk + tig + 4)];
            }
#pragma unroll
            for (int mi = 0; mi < 4; mi++)
#pragma unroll
                for (int nj = 0; nj < 4; nj++)
                    mma_tf32(acc[mi][nj], av[mi], bv[nj][0], bv[nj][1]);
        }

        stage++; if (stage >= NSTAGE) stage -= NSTAGE;
    }

    // epilogue
#pragma unroll
    for (int mi = 0; mi < 4; mi++) {
        const int r = m0 + wm * 64 + 16 * mi + gid;
#pragma unroll
        for (int nj = 0; nj < 4; nj++) {
            const int c = n0 + wn * 32 + 8 * nj + 2 * tig;
            if (OUT_TF32) {
                unsigned* C = (unsigned*)Cv;
                *(uint2*)(C + (size_t)r * N + c) =
                    make_uint2(f2tf(acc[mi][nj][0]), f2tf(acc[mi][nj][1]));
                *(uint2*)(C + (size_t)(r + 8) * N + c) =
                    make_uint2(f2tf(acc[mi][nj][2]), f2tf(acc[mi][nj][3]));
            } else {
                float* C = (float*)Cv;
                *(float2*)(C + (size_t)r * N + c) =
                    make_float2(acc[mi][nj][0], acc[mi][nj][1]);
                *(float2*)(C + (size_t)(r + 8) * N + c) =
                    make_float2(acc[mi][nj][2], acc[mi][nj][3]);
            }
        }
    }
}

// ---------------------------------------------------------------------------
// Causal flash attention (R3 configuration: 64-query tiles, 128 threads,
// double-buffered cp.async K/V) — the best-measured variant.
// ---------------------------------------------------------------------------
#define KS_STRIDE 68
#define VS_STRIDE 72
#define PS_STRIDE 68
#define KS_ELEMS (64 * KS_STRIDE)
#define VS_ELEMS (64 * VS_STRIDE)
#define SMEM_ATTN ((2 * KS_ELEMS + 2 * VS_ELEMS + 64 * PS_STRIDE) * 4)

__global__ __launch_bounds__(128)
void attn_tf32(const unsigned* __restrict__ qkv, unsigned* __restrict__ out) {
    extern __shared__ unsigned sma[];
    unsigned* KsF = sma;
    unsigned* VsF = sma + 2 * KS_ELEMS;
    unsigned* Ps  = sma + 2 * KS_ELEMS + 2 * VS_ELEMS;

    const int qt   = gridDim.x - 1 - blockIdx.x;   // heavy tiles first
    const int h    = blockIdx.y;
    const int b    = blockIdx.z;
    const int t    = threadIdx.x;
    const int lane = t & 31;
    const int w    = t >> 5;
    const int gid  = lane >> 2;
    const int tig  = lane & 3;
    const int q0   = qt * 64;

    const int lrow = t >> 4;
    const int lc4  = (t & 15) * 4;

    const unsigned* kbase = qkv + (size_t)b * SEQ * QKV_W + D_MODEL + h * HD;
    const unsigned* vbase = kbase + D_MODEL;

    // prologue: Q tile + K/V tile 0
    {
        const unsigned* qp = qkv + (size_t)(b * SEQ + q0) * QKV_W + h * HD;
#pragma unroll
        for (int p = 0; p < 8; p++) {
            const int row = p * 8 + lrow;
            cp_async16(&Ps[row * PS_STRIDE + lc4], qp + (size_t)row * QKV_W + lc4);
            cp_async16(&KsF[row * KS_STRIDE + lc4], kbase + (size_t)row * QKV_W + lc4);
            cp_async16(&VsF[row * VS_STRIDE + lc4], vbase + (size_t)row * QKV_W + lc4);
        }
    }
    CP_COMMIT();
    CP_WAIT0();
    __syncthreads();

    // Q fragments -> registers (scale by exact power of two)
    unsigned qf[8][4];
    {
        const int r0 = (16 * w + gid) * PS_STRIDE;
        const int r1 = (16 * w + gid + 8) * PS_STRIDE;
#pragma unroll
        for (int s = 0; s < 8; s++) {
            qf[s][0] = __float_as_uint(__uint_as_float(Ps[r0 + 8 * s + tig]) * 0.125f);
            qf[s][1] = __float_as_uint(__uint_as_float(Ps[r1 + 8 * s + tig]) * 0.125f);
            qf[s][2] = __float_as_uint(__uint_as_float(Ps[r0 + 8 * s + tig + 4]) * 0.125f);
            qf[s][3] = __float_as_uint(__uint_as_float(Ps[r1 + 8 * s + tig + 4]) * 0.125f);
        }
    }

    float o[8][4];
#pragma unroll
    for (int j = 0; j < 8; j++)
#pragma unroll
        for (int e = 0; e < 4; e++) o[j][e] = 0.f;
    float m0 = -1e30f, m1 = -1e30f, l0 = 0.f, l1 = 0.f;

    const int row0 = q0 + 16 * w + gid;

    for (int jt = 0; jt <= qt; jt++) {
        const int cur = jt & 1;
        if (jt + 1 <= qt) {
            const int nb = cur ^ 1;
            const unsigned* kp = kbase + (size_t)(jt + 1) * 64 * QKV_W;
            const unsigned* vp = vbase + (size_t)(jt + 1) * 64 * QKV_W;
#pragma unroll
            for (int p = 0; p < 8; p++) {
                const int row = p * 8 + lrow;
                cp_async16(&KsF[nb * KS_ELEMS + row * KS_STRIDE + lc4],
                           kp + (size_t)row * QKV_W + lc4);
                cp_async16(&VsF[nb * VS_ELEMS + row * VS_STRIDE + lc4],
                           vp + (size_t)row * QKV_W + lc4);
            }
        }
        CP_COMMIT();
        CP_WAIT1();
        __syncthreads();

        const unsigned* Ks = KsF + cur * KS_ELEMS;
        const unsigned* Vs = VsF + cur * VS_ELEMS;
        const int k0 = jt * 64;

        // S = Q K^T
        float sacc[8][4];
#pragma unroll
        for (int j = 0; j < 8; j++)
#pragma unroll
            for (int e = 0; e < 4; e++) sacc[j][e] = 0.f;

#pragma unroll
        for (int s = 0; s < 8; s++) {
#pragma unroll
            for (int j = 0; j < 8; j++) {
                const int kr = (8 * j + gid) * KS_STRIDE + 8 * s + tig;
                mma_tf32(sacc[j], qf[s], Ks[kr], Ks[kr + 4]);
            }
        }

        // mask + row max
        float mt0 = -1e30f, mt1 = -1e30f;
#pragma unroll
        for (int j = 0; j < 8; j++) {
            const int cb = k0 + 8 * j + 2 * tig;
            if (jt == qt) {
                if (cb     > row0)     sacc[j][0] = -1e30f;
                if (cb + 1 > row0)     sacc[j][1] = -1e30f;
                if (cb     > row0 + 8) sacc[j][2] = -1e30f;
                if (cb + 1 > row0 + 8) sacc[j][3] = -1e30f;
            }
            mt0 = fmaxf(mt0, fmaxf(sacc[j][0], sacc[j][1]));
            mt1 = fmaxf(mt1, fmaxf(sacc[j][2], sacc[j][3]));
        }
        mt0 = fmaxf(mt0, __shfl_xor_sync(0xffffffffu, mt0, 1));
        mt0 = fmaxf(mt0, __shfl_xor_sync(0xffffffffu, mt0, 2));
        mt1 = fmaxf(mt1, __shfl_xor_sync(0xffffffffu, mt1, 1));
        mt1 = fmaxf(mt1, __shfl_xor_sync(0xffffffffu, mt1, 2));

        const float mn0 = fmaxf(m0, mt0);
        const float mn1 = fmaxf(m1, mt1);
        const float al0 = __expf(m0 - mn0);
        const float al1 = __expf(m1 - mn1);
        m0 = mn0; m1 = mn1;

        // P = exp(S - m) -> warp-private Ps rows (tf32), row sums
        float ls0 = 0.f, ls1 = 0.f;
        {
            const int pr0 = (16 * w + gid) * PS_STRIDE;
            const int pr1 = (16 * w + gid + 8) * PS_STRIDE;
#pragma unroll
            for (int j = 0; j < 8; j++) {
                const int c = 8 * j + 2 * tig;
                float p00 = __expf(sacc[j][0] - mn0);
                float p01 = __expf(sacc[j][1] - mn0);
                float p10 = __expf(sacc[j][2] - mn1);
                float p11 = __expf(sacc[j][3] - mn1);
                ls0 += p00 + p01;
                ls1 += p10 + p11;
                Ps[pr0 + c]     = f2tf(p00);
                Ps[pr0 + c + 1] = f2tf(p01);
                Ps[pr1 + c]     = f2tf(p10);
                Ps[pr1 + c + 1] = f2tf(p11);
            }
        }
        ls0 += __shfl_xor_sync(0xffffffffu, ls0, 1);
        ls0 += __shfl_xor_sync(0xffffffffu, ls0, 2);
        ls1 += __shfl_xor_sync(0xffffffffu, ls1, 1);
        ls1 += __shfl_xor_sync(0xffffffffu, ls1, 2);
        l0 = l0 * al0 + ls0;
        l1 = l1 * al1 + ls1;

#pragma unroll
        for (int j = 0; j < 8; j++) {
            o[j][0] *= al0; o[j][1] *= al0;
            o[j][2] *= al1; o[j][3] *= al1;
        }
        __syncwarp();

        // O += P V
#pragma unroll
        for (int s = 0; s < 8; s++) {
            unsigned pa[4];
            const int pr0 = (16 * w + gid) * PS_STRIDE + 8 * s;
            const int pr1 = (16 * w + gid + 8) * PS_STRIDE + 8 * s;
            pa[0] = Ps[pr0 + tig];
            pa[1] = Ps[pr1 + tig];
            pa[2] = Ps[pr0 + tig + 4];
            pa[3] = Ps[pr1 + tig + 4];
#pragma unroll
            for (int j = 0; j < 8; j++) {
                const int vb = (8 * s + tig) * VS_STRIDE + 8 * j + gid;
                mma_tf32(o[j], pa, Vs[vb], Vs[vb + 4 * VS_STRIDE]);
            }
        }
        __syncthreads();
    }

    // epilogue -> tf32 bits for the output projection
    const float i0 = 1.f / l0;
    const float i1 = 1.f / l1;
    unsigned* op0 = out + (size_t)(b * SEQ + row0) * D_MODEL + h * HD;
    unsigned* op1 = op0 + (size_t)8 * D_MODEL;
#pragma unroll
    for (int j = 0; j < 8; j++) {
        const int c = 8 * j + 2 * tig;
        *(uint2*)(op0 + c) = make_uint2(f2tf(o[j][0] * i0), f2tf(o[j][1] * i0));
        *(uint2*)(op1 + c) = make_uint2(f2tf(o[j][2] * i1), f2tf(o[j][3] * i1));
    }
}

extern "C" void kernel_launch(void* const* d_in, const int* in_sizes, int n_in,
                              void* d_out, int out_size) {
    const float* x     = (const float*)d_in[0];
    const float* w_qkv = (const float*)d_in[1];
    const float* w_o   = (const float*)d_in[2];
    float* out         = (float*)d_out;

    unsigned *qkv, *ao, *xc, *wq, *wo;
    cudaGetSymbolAddress((void**)&qkv, g_qkv);
    cudaGetSymbolAddress((void**)&ao,  g_ao);
    cudaGetSymbolAddress((void**)&xc,  g_xc);
    cudaGetSymbolAddress((void**)&wq,  g_wq);
    cudaGetSymbolAddress((void**)&wo,  g_wo);

    static bool attr_set = false;
    if (!attr_set) {
        cudaFuncSetAttribute(gemm_tt<true>,  cudaFuncAttributeMaxDynamicSharedMemorySize, SMEM_GEMM);
        cudaFuncSetAttribute(gemm_tt<false>, cudaFuncAttributeMaxDynamicSharedMemorySize, SMEM_GEMM);
        cudaFuncSetAttribute(attn_tf32, cudaFuncAttributeMaxDynamicSharedMemorySize, SMEM_ATTN);
        attr_set = true;
    }

    conv_tf32<<<CONV_BLOCKS, 256>>>((const float4*)x, (const float4*)w_qkv, (const float4*)w_o,
                                    (uint4*)xc, (uint4*)wq, (uint4*)wo);

    gemm_tt<true><<<dim3(QKV_W / 128, M_TOT / 128), 256, SMEM_GEMM>>>(xc, wq, qkv, M_TOT, QKV_W, D_MODEL);

    attn_tf32<<<dim3(SEQ / 64, NHEAD, BATCH), 128, SMEM_ATTN>>>(qkv, ao);

    gemm_tt<false><<<dim3(D_MODEL / 128, M_TOT / 128), 256, SMEM_GEMM>>>(ao, wo, out, M_TOT, D_MODEL, D_MODEL);
}

// round 9
// speedup vs baseline: 1.5362x; 1.4303x over previous
#include <cuda_runtime.h>
#include <cuda_fp16.h>
#include <cstdint>

#define D_MODEL 1024
#define NHEAD   16
#define HD      64
#define SEQ     2048
#define BATCH   2
#define M_TOT   (BATCH * SEQ)   // 4096
#define QKV_W   (3 * D_MODEL)   // 3072

// Scratch (no cudaMalloc allowed).
__device__ __half   g_qkh[(size_t)M_TOT * 2 * D_MODEL];  // Q|K fp16 [4096][2048]
__device__ unsigned g_v  [(size_t)M_TOT * D_MODEL];      // V tf32  [4096][1024]
__device__ __half   g_ao [(size_t)M_TOT * D_MODEL];      // attn out fp16
__device__ __half   g_xh [(size_t)M_TOT * D_MODEL];      // x -> fp16
__device__ __half   g_wqh[(size_t)QKV_W * D_MODEL];      // w_qkv -> fp16
__device__ __half   g_woh[(size_t)D_MODEL * D_MODEL];    // w_o -> fp16

__device__ __forceinline__ unsigned f2tf(float f) {
    unsigned u;
    asm("cvt.rna.tf32.f32 %0, %1;" : "=r"(u) : "f"(f));
    return u;
}

// fp16 mma: D(fp32) += A(f16 m16k16 row) x B(f16 k16n8 col)
__device__ __forceinline__ void mma_f16(float* c, const unsigned* a,
                                        unsigned b0, unsigned b1) {
    asm volatile(
        "mma.sync.aligned.m16n8k16.row.col.f32.f16.f16.f32 "
        "{%0,%1,%2,%3},{%4,%5,%6,%7},{%8,%9},{%0,%1,%2,%3};\n"
        : "+f"(c[0]), "+f"(c[1]), "+f"(c[2]), "+f"(c[3])
        : "r"(a[0]), "r"(a[1]), "r"(a[2]), "r"(a[3]), "r"(b0), "r"(b1));
}

// tf32 mma (PV path in attention)
__device__ __forceinline__ void mma_tf32(float* c, const unsigned* a,
                                         unsigned b0, unsigned b1) {
    asm volatile(
        "mma.sync.aligned.m16n8k8.row.col.f32.tf32.tf32.f32 "
        "{%0,%1,%2,%3},{%4,%5,%6,%7},{%8,%9},{%0,%1,%2,%3};\n"
        : "+f"(c[0]), "+f"(c[1]), "+f"(c[2]), "+f"(c[3])
        : "r"(a[0]), "r"(a[1]), "r"(a[2]), "r"(a[3]), "r"(b0), "r"(b1));
}

__device__ __forceinline__ void cp_async16(void* smem_dst, const void* gmem_src) {
    unsigned s = (unsigned)__cvta_generic_to_shared(smem_dst);
    asm volatile("cp.async.cg.shared.global [%0], [%1], 16;\n" :: "r"(s), "l"(gmem_src));
}
#define CP_COMMIT() asm volatile("cp.async.commit_group;\n" ::: "memory")
#define CP_WAIT1()  asm volatile("cp.async.wait_group 1;\n" ::: "memory")
#define CP_WAIT0()  asm volatile("cp.async.wait_group 0;\n" ::: "memory")

// ---------------------------------------------------------------------------
// fp32 -> fp16 pre-pass (x, w_qkv, w_o)
// ---------------------------------------------------------------------------
#define XC_F4 ((M_TOT * D_MODEL) / 4)
#define WQ_F4 ((QKV_W * D_MODEL) / 4)
#define WO_F4 ((D_MODEL * D_MODEL) / 4)
#define CONV_BLOCKS ((XC_F4 + WQ_F4 + WO_F4) / 256)

__global__ void conv_h(const float4* __restrict__ x,
                       const float4* __restrict__ wq,
                       const float4* __restrict__ wo,
                       uint2* __restrict__ ox,
                       uint2* __restrict__ owq,
                       uint2* __restrict__ owo) {
    const int idx = blockIdx.x * 256 + threadIdx.x;
    const float4* src;
    uint2* dst;
    int i;
    if (idx < XC_F4)                { src = x;  dst = ox;  i = idx; }
    else if (idx < XC_F4 + WQ_F4)   { src = wq; dst = owq; i = idx - XC_F4; }
    else                            { src = wo; dst = owo; i = idx - XC_F4 - WQ_F4; }
    float4 v = src[i];
    __half2 lo = __floats2half2_rn(v.x, v.y);
    __half2 hi = __floats2half2_rn(v.z, v.w);
    dst[i] = make_uint2(*(unsigned*)&lo, *(unsigned*)&hi);
}

// ---------------------------------------------------------------------------
// fp16 GEMM: C[m][n] = sum_k A[m][k]*B[n][k] (A:[M,K], B:[N,K] fp16).
// 128x128 block tile, K-tile 32 halves, 256 threads (8 warps, 64x32 tiles),
// 3-stage cp.async pipeline, padded smem rows (20 u32, conflict-free).
// MODE 0: fp32 out -> C0.  MODE 1: cols<2048 -> fp16 C0 (Q|K, stride 2048),
//                          cols>=2048 -> tf32 C1 (V, stride 1024).
// ---------------------------------------------------------------------------
#define NSTAGE 3
#define GSTR 20                 // u32 per smem row (16 data + 4 pad)
#define GTILE (128 * GSTR)
#define SMEM_GEMM (2 * NSTAGE * GTILE * 4)   // 61440 B

template <int MODE>
__global__ __launch_bounds__(256, 2)
void gemm_h(const __half* __restrict__ A, const __half* __restrict__ B,
            void* __restrict__ C0, void* __restrict__ C1, int M, int N, int K) {
    extern __shared__ unsigned smg[];
    unsigned* Abuf = smg;
    unsigned* Bbuf = smg + NSTAGE * GTILE;

    const int t    = threadIdx.x;
    const int lane = t & 31;
    const int w    = t >> 5;
    const int gid  = lane >> 2;
    const int tig  = lane & 3;
    const int wm   = w & 1;
    const int wn   = w >> 1;
    const int m0   = blockIdx.y * 128;
    const int n0   = blockIdx.x * 128;

    float acc[4][4][4];
#pragma unroll
    for (int i = 0; i < 4; i++)
#pragma unroll
        for (int j = 0; j < 4; j++)
#pragma unroll
            for (int e = 0; e < 4; e++) acc[i][j][e] = 0.f;

    const int nkt = K / 32;

    // one K-tile (32 halves wide): 128 rows x 4 chunks(16B) per operand
    auto issue = [&](int stage, int kt) {
        unsigned* as = Abuf + stage * GTILE;
        unsigned* bs = Bbuf + stage * GTILE;
        const __half* Ag = A + (size_t)m0 * K + kt * 32;
        const __half* Bg = B + (size_t)n0 * K + kt * 32;
#pragma unroll
        for (int i = 0; i < 2; i++) {
            const int c = t + i * 256;           // 0..511
            const int row = c >> 2, cc = c & 3;
            cp_async16(&as[row * GSTR + cc * 4], Ag + (size_t)row * K + cc * 8);
            cp_async16(&bs[row * GSTR + cc * 4], Bg + (size_t)row * K + cc * 8);
        }
    };

    issue(0, 0); CP_COMMIT();
    issue(1, 1); CP_COMMIT();

    int stage = 0;
    for (int kt = 0; kt < nkt; kt++) {
        if (kt + 1 < nkt) { CP_WAIT1(); } else { CP_WAIT0(); }
        __syncthreads();          // tile kt ready; stage (kt+2)%3 free

        if (kt + 2 < nkt) {
            int ns = stage + 2; if (ns >= NSTAGE) ns -= NSTAGE;
            issue(ns, kt + 2);
            CP_COMMIT();
        }

        const unsigned* As = Abuf + stage * GTILE;
        const unsigned* Bs = Bbuf + stage * GTILE;
        const int am = wm * 64;
        const int bn = wn * 32;
#pragma unroll
        for (int s = 0; s < 2; s++) {           // two k16 steps per tile
            const int kk = s * 8;
            unsigned av[4][4];
#pragma unroll
            for (int mi = 0; mi < 4; mi++) {
                const int r  = (am + 16 * mi + gid) * GSTR;
                const int r8 = r + 8 * GSTR;
                av[mi][0] = As[r + kk + tig];
                av[mi][1] = As[r8 + kk + tig];
                av[mi][2] = As[r + kk + tig + 4];
                av[mi][3] = As[r8 + kk + tig + 4];
            }
            unsigned bv[4][2];
#pragma unroll
            for (int nj = 0; nj < 4; nj++) {
                const int r = (bn + 8 * nj + gid) * GSTR;
                bv[nj][0] = Bs[r + kk + tig];
                bv[nj][1] = Bs[r + kk + tig + 4];
            }
#pragma unroll
            for (int mi = 0; mi < 4; mi++)
#pragma unroll
                for (int nj = 0; nj < 4; nj++)
                    mma_f16(acc[mi][nj], av[mi], bv[nj][0], bv[nj][1]);
        }
        __syncthreads();          // done reading stage before it is refilled

        stage++; if (stage >= NSTAGE) stage -= NSTAGE;
    }

    // epilogue
#pragma unroll
    for (int mi = 0; mi < 4; mi++) {
        const int r = m0 + wm * 64 + 16 * mi + gid;
#pragma unroll
        for (int nj = 0; nj < 4; nj++) {
            const int c = n0 + wn * 32 + 8 * nj + 2 * tig;
            if (MODE == 0) {
                float* C = (float*)C0;
                *(float2*)(C + (size_t)r * N + c) =
                    make_float2(acc[mi][nj][0], acc[mi][nj][1]);
                *(float2*)(C + (size_t)(r + 8) * N + c) =
                    make_float2(acc[mi][nj][2], acc[mi][nj][3]);
            } else {
                if (n0 < 2 * D_MODEL) {   // Q|K -> fp16
                    __half2* C = (__half2*)C0;
                    __half2 v0 = __floats2half2_rn(acc[mi][nj][0], acc[mi][nj][1]);
                    __half2 v1 = __floats2half2_rn(acc[mi][nj][2], acc[mi][nj][3]);
                    C[((size_t)r * 2048 + c) >> 1]       = v0;
                    C[((size_t)(r + 8) * 2048 + c) >> 1] = v1;
                } else {                  // V -> tf32
                    unsigned* V = (unsigned*)C1;
                    const int cv = c - 2 * D_MODEL;
                    *(uint2*)(V + (size_t)r * D_MODEL + cv) =
                        make_uint2(f2tf(acc[mi][nj][0]), f2tf(acc[mi][nj][1]));
                    *(uint2*)(V + (size_t)(r + 8) * D_MODEL + cv) =
                        make_uint2(f2tf(acc[mi][nj][2]), f2tf(acc[mi][nj][3]));
                }
            }
        }
    }
}

// ---------------------------------------------------------------------------
// Causal flash attention. Q,K fp16 (S via m16n8k16), V/P tf32 (PV m16n8k8).
// 64-query tiles, 128 threads, double-buffered cp.async K/V.
// K/Q rows: 64 halves = 32 u32 data, stride 36 (conflict-free).
// ---------------------------------------------------------------------------
#define AKS 36                      // K tile row stride (u32: 32 data + 4 pad)
#define AKS_ELEMS (64 * AKS)
#define AVS 72                      // V tile row stride (u32 tf32)
#define AVS_ELEMS (64 * AVS)
#define AQS 36                      // Q staging row stride (u32)
#define PS_STRIDE 68
#define SMEM_ATTN ((2 * AKS_ELEMS + 2 * AVS_ELEMS + 64 * AQS + 64 * PS_STRIDE) * 4)

__global__ __launch_bounds__(128)
void attn_h(const __half* __restrict__ qk, const unsigned* __restrict__ v,
            __half* __restrict__ out) {
    extern __shared__ unsigned sma[];
    unsigned* KsB = sma;                                     // [2][64][AKS]
    unsigned* VsB = sma + 2 * AKS_ELEMS;                     // [2][64][AVS]
    unsigned* Qs  = sma + 2 * AKS_ELEMS + 2 * AVS_ELEMS;     // [64][AQS]
    unsigned* Ps  = Qs + 64 * AQS;                           // [64][PS_STRIDE]

    const int qt   = gridDim.x - 1 - blockIdx.x;      // heavy tiles first
    const int h    = blockIdx.y;
    const int b    = blockIdx.z;
    const int t    = threadIdx.x;
    const int lane = t & 31;
    const int w    = t >> 5;
    const int gid  = lane >> 2;
    const int tig  = lane & 3;
    const int q0   = qt * 64;

    const __half* kbase = qk + (size_t)(b * SEQ) * 2048 + D_MODEL + h * HD;
    const unsigned* vbase = v + (size_t)(b * SEQ) * D_MODEL + h * HD;

    // K/V tile loader into buffer nb for key tile jt
    auto load_kv = [&](int nb, int jt) {
        const __half* kp = kbase + (size_t)jt * 64 * 2048;
        const unsigned* vp = vbase + (size_t)jt * 64 * D_MODEL;
#pragma unroll
        for (int i = 0; i < 4; i++) {       // K: 64 rows x 8 chunks = 512
            const int c = t + i * 128;
            const int row = c >> 3, cc = c & 7;
            cp_async16(&KsB[nb * AKS_ELEMS + row * AKS + cc * 4],
                       kp + (size_t)row * 2048 + cc * 8);
        }
#pragma unroll
        for (int i = 0; i < 8; i++) {       // V: 64 rows x 16 chunks = 1024
            const int c = t + i * 128;
            const int row = c >> 4, cc = c & 15;
            cp_async16(&VsB[nb * AVS_ELEMS + row * AVS + cc * 4],
                       vp + (size_t)row * D_MODEL + cc * 4);
        }
    };

    // prologue: Q tile + K/V tile 0
    {
        const __half* qp = qk + (size_t)(b * SEQ + q0) * 2048 + h * HD;
#pragma unroll
        for (int i = 0; i < 4; i++) {       // Q: 64 rows x 8 chunks = 512
            const int c = t + i * 128;
            const int row = c >> 3, cc = c & 7;
            cp_async16(&Qs[row * AQS + cc * 4], qp + (size_t)row * 2048 + cc * 8);
        }
        load_kv(0, 0);
    }
    CP_COMMIT();
    CP_WAIT0();
    __syncthreads();

    // Q fragments -> registers, scaled by 0.125 (exact in fp16)
    unsigned qf[4][4];
    {
        const __half2 sc = __float2half2_rn(0.125f);
        const int r0 = (16 * w + gid) * AQS;
        const int r1 = (16 * w + gid + 8) * AQS;
#pragma unroll
        for (int s = 0; s < 4; s++) {
            unsigned u0 = Qs[r0 + 8 * s + tig];
            unsigned u1 = Qs[r1 + 8 * s + tig];
            unsigned u2 = Qs[r0 + 8 * s + tig + 4];
            unsigned u3 = Qs[r1 + 8 * s + tig + 4];
            __half2 h0 = __hmul2(*(__half2*)&u0, sc);
            __half2 h1 = __hmul2(*(__half2*)&u1, sc);
            __half2 h2 = __hmul2(*(__half2*)&u2, sc);
            __half2 h3 = __hmul2(*(__half2*)&u3, sc);
            qf[s][0] = *(unsigned*)&h0;
            qf[s][1] = *(unsigned*)&h1;
            qf[s][2] = *(unsigned*)&h2;
            qf[s][3] = *(unsigned*)&h3;
        }
    }

    float o[8][4];
#pragma unroll
    for (int j = 0; j < 8; j++)
#pragma unroll
        for (int e = 0; e < 4; e++) o[j][e] = 0.f;
    float m0 = -1e30f, m1 = -1e30f, l0 = 0.f, l1 = 0.f;

    const int row0 = q0 + 16 * w + gid;

    for (int jt = 0; jt <= qt; jt++) {
        const int cur = jt & 1;
        if (jt + 1 <= qt) {
            load_kv(cur ^ 1, jt + 1);
            CP_COMMIT();
            CP_WAIT1();           // tile jt's group complete
        } else {
            CP_WAIT0();           // last tile: everything complete
        }
        __syncthreads();

        const unsigned* Ks = KsB + cur * AKS_ELEMS;
        const unsigned* Vs = VsB + cur * AVS_ELEMS;
        const int k0 = jt * 64;

        // S = Q K^T (fp16, 4 k16-steps)
        float sacc[8][4];
#pragma unroll
        for (int j = 0; j < 8; j++)
#pragma unroll
            for (int e = 0; e < 4; e++) sacc[j][e] = 0.f;

#pragma unroll
        for (int s = 0; s < 4; s++) {
#pragma unroll
            for (int j = 0; j < 8; j++) {
                const int kr = (8 * j + gid) * AKS + 8 * s + tig;
                mma_f16(sacc[j], qf[s], Ks[kr], Ks[kr + 4]);
            }
        }

        // mask + row max
        float mt0 = -1e30f, mt1 = -1e30f;
#pragma unroll
        for (int j = 0; j < 8; j++) {
            const int cb = k0 + 8 * j + 2 * tig;
            if (jt == qt) {
                if (cb     > row0)     sacc[j][0] = -1e30f;
                if (cb + 1 > row0)     sacc[j][1] = -1e30f;
                if (cb     > row0 + 8) sacc[j][2] = -1e30f;
                if (cb + 1 > row0 + 8) sacc[j][3] = -1e30f;
            }
            mt0 = fmaxf(mt0, fmaxf(sacc[j][0], sacc[j][1]));
            mt1 = fmaxf(mt1, fmaxf(sacc[j][2], sacc[j][3]));
        }
        mt0 = fmaxf(mt0, __shfl_xor_sync(0xffffffffu, mt0, 1));
        mt0 = fmaxf(mt0, __shfl_xor_sync(0xffffffffu, mt0, 2));
        mt1 = fmaxf(mt1, __shfl_xor_sync(0xffffffffu, mt1, 1));
        mt1 = fmaxf(mt1, __shfl_xor_sync(0xffffffffu, mt1, 2));

        const float mn0 = fmaxf(m0, mt0);
        const float mn1 = fmaxf(m1, mt1);
        const float al0 = __expf(m0 - mn0);
        const float al1 = __expf(m1 - mn1);
        m0 = mn0; m1 = mn1;

        // P = exp(S - m) -> Ps (tf32), row sums
        float ls0 = 0.f, ls1 = 0.f;
        {
            const int pr0 = (16 * w + gid) * PS_STRIDE;
            const int pr1 = (16 * w + gid + 8) * PS_STRIDE;
#pragma unroll
            for (int j = 0; j < 8; j++) {
                const int c = 8 * j + 2 * tig;
                float p00 = __expf(sacc[j][0] - mn0);
                float p01 = __expf(sacc[j][1] - mn0);
                float p10 = __expf(sacc[j][2] - mn1);
                float p11 = __expf(sacc[j][3] - mn1);
                ls0 += p00 + p01;
                ls1 += p10 + p11;
                Ps[pr0 + c]     = f2tf(p00);
                Ps[pr0 + c + 1] = f2tf(p01);
                Ps[pr1 + c]     = f2tf(p10);
                Ps[pr1 + c + 1] = f2tf(p11);
            }
        }
        ls0 += __shfl_xor_sync(0xffffffffu, ls0, 1);
        ls0 += __shfl_xor_sync(0xffffffffu, ls0, 2);
        ls1 += __shfl_xor_sync(0xffffffffu, ls1, 1);
        ls1 += __shfl_xor_sync(0xffffffffu, ls1, 2);
        l0 = l0 * al0 + ls0;
        l1 = l1 * al1 + ls1;

#pragma unroll
        for (int j = 0; j < 8; j++) {
            o[j][0] *= al0; o[j][1] *= al0;
            o[j][2] *= al1; o[j][3] *= al1;
        }
        __syncwarp();

        // O += P V (tf32)
#pragma unroll
        for (int s = 0; s < 8; s++) {
            unsigned pa[4];
            const int pr0 = (16 * w + gid) * PS_STRIDE + 8 * s;
            const int pr1 = (16 * w + gid + 8) * PS_STRIDE + 8 * s;
            pa[0] = Ps[pr0 + tig];
            pa[1] = Ps[pr1 + tig];
            pa[2] = Ps[pr0 + tig + 4];
            pa[3] = Ps[pr1 + tig + 4];
#pragma unroll
            for (int j = 0; j < 8; j++) {
                const int vb = (8 * s + tig) * AVS + 8 * j + gid;
                mma_tf32(o[j], pa, Vs[vb], Vs[vb + 4 * AVS]);
            }
        }
        __syncthreads();    // done reading cur before overwrite
    }

    // epilogue -> fp16 for the output projection
    const float i0 = 1.f / l0;
    const float i1 = 1.f / l1;
    __half2* op0 = (__half2*)(out + (size_t)(b * SEQ + row0) * D_MODEL + h * HD);
    __half2* op1 = (__half2*)(out + (size_t)(b * SEQ + row0 + 8) * D_MODEL + h * HD);
#pragma unroll
    for (int j = 0; j < 8; j++) {
        const int c = (8 * j + 2 * tig) >> 1;
        op0[c] = __floats2half2_rn(o[j][0] * i0, o[j][1] * i0);
        op1[c] = __floats2half2_rn(o[j][2] * i1, o[j][3] * i1);
    }
}

extern "C" void kernel_launch(void* const* d_in, const int* in_sizes, int n_in,
                              void* d_out, int out_size) {
    const float* x     = (const float*)d_in[0];
    const float* w_qkv = (const float*)d_in[1];
    const float* w_o   = (const float*)d_in[2];
    float* out         = (float*)d_out;

    __half *qkh, *ao, *xh, *wqh, *woh;
    unsigned *v;
    cudaGetSymbolAddress((void**)&qkh, g_qkh);
    cudaGetSymbolAddress((void**)&v,   g_v);
    cudaGetSymbolAddress((void**)&ao,  g_ao);
    cudaGetSymbolAddress((void**)&xh,  g_xh);
    cudaGetSymbolAddress((void**)&wqh, g_wqh);
    cudaGetSymbolAddress((void**)&woh, g_woh);

    static bool attr_set = false;
    if (!attr_set) {
        cudaFuncSetAttribute(gemm_h<0>, cudaFuncAttributeMaxDynamicSharedMemorySize, SMEM_GEMM);
        cudaFuncSetAttribute(gemm_h<1>, cudaFuncAttributeMaxDynamicSharedMemorySize, SMEM_GEMM);
        cudaFuncSetAttribute(attn_h, cudaFuncAttributeMaxDynamicSharedMemorySize, SMEM_ATTN);
        attr_set = true;
    }

    // 0) fp32 -> fp16 pre-pass
    conv_h<<<CONV_BLOCKS, 256>>>((const float4*)x, (const float4*)w_qkv, (const float4*)w_o,
                                 (uint2*)xh, (uint2*)wqh, (uint2*)woh);

    // 1) QKV projection (fp16 mma): Q|K -> fp16, V -> tf32
    gemm_h<1><<<dim3(QKV_W / 128, M_TOT / 128), 256, SMEM_GEMM>>>(
        xh, wqh, qkh, v, M_TOT, QKV_W, D_MODEL);

    // 2) causal attention -> fp16
    attn_h<<<dim3(SEQ / 64, NHEAD, BATCH), 128, SMEM_ATTN>>>(qkh, v, ao);

    // 3) output projection (fp16 mma) -> fp32
    gemm_h<0><<<dim3(D_MODEL / 128, M_TOT / 128), 256, SMEM_GEMM>>>(
        ao, woh, out, nullptr, M_TOT, D_MODEL, D_MODEL);
}

// round 10
// speedup vs baseline: 1.9168x; 1.2477x over previous
#include <cuda_runtime.h>
#include <cuda_fp16.h>
#include <cstdint>

#define D_MODEL 1024
#define NHEAD   16
#define HD      64
#define SEQ     2048
#define BATCH   2
#define M_TOT   (BATCH * SEQ)   // 4096
#define QKV_W   (3 * D_MODEL)   // 3072

// Scratch (no cudaMalloc allowed).
__device__ __half g_qkh[(size_t)M_TOT * 2 * D_MODEL];  // Q|K fp16 [4096][2048]
__device__ __half g_vt [(size_t)M_TOT * D_MODEL];      // V^T fp16 [(b*1024+d)][2048 s]
__device__ __half g_ao [(size_t)M_TOT * D_MODEL];      // attn out fp16
__device__ __half g_xh [(size_t)M_TOT * D_MODEL];      // x -> fp16
__device__ __half g_wqh[(size_t)QKV_W * D_MODEL];      // w_qkv -> fp16
__device__ __half g_woh[(size_t)D_MODEL * D_MODEL];    // w_o -> fp16

// fp16 mma: D(fp32) += A(f16 m16k16 row) x B(f16 k16n8 col)
__device__ __forceinline__ void mma_f16(float* c, const unsigned* a,
                                        unsigned b0, unsigned b1) {
    asm volatile(
        "mma.sync.aligned.m16n8k16.row.col.f32.f16.f16.f32 "
        "{%0,%1,%2,%3},{%4,%5,%6,%7},{%8,%9},{%0,%1,%2,%3};\n"
        : "+f"(c[0]), "+f"(c[1]), "+f"(c[2]), "+f"(c[3])
        : "r"(a[0]), "r"(a[1]), "r"(a[2]), "r"(a[3]), "r"(b0), "r"(b1));
}

__device__ __forceinline__ void cp_async16(void* smem_dst, const void* gmem_src) {
    unsigned s = (unsigned)__cvta_generic_to_shared(smem_dst);
    asm volatile("cp.async.cg.shared.global [%0], [%1], 16;\n" :: "r"(s), "l"(gmem_src));
}
#define CP_COMMIT() asm volatile("cp.async.commit_group;\n" ::: "memory")
#define CP_WAIT1()  asm volatile("cp.async.wait_group 1;\n" ::: "memory")
#define CP_WAIT0()  asm volatile("cp.async.wait_group 0;\n" ::: "memory")

// ---------------------------------------------------------------------------
// fp32 -> fp16 pre-pass (x, w_qkv, w_o)
// ---------------------------------------------------------------------------
#define XC_F4 ((M_TOT * D_MODEL) / 4)
#define WQ_F4 ((QKV_W * D_MODEL) / 4)
#define WO_F4 ((D_MODEL * D_MODEL) / 4)
#define CONV_BLOCKS ((XC_F4 + WQ_F4 + WO_F4) / 256)

__global__ void conv_h(const float4* __restrict__ x,
                       const float4* __restrict__ wq,
                       const float4* __restrict__ wo,
                       uint2* __restrict__ ox,
                       uint2* __restrict__ owq,
                       uint2* __restrict__ owo) {
    const int idx = blockIdx.x * 256 + threadIdx.x;
    const float4* src;
    uint2* dst;
    int i;
    if (idx < XC_F4)                { src = x;  dst = ox;  i = idx; }
    else if (idx < XC_F4 + WQ_F4)   { src = wq; dst = owq; i = idx - XC_F4; }
    else                            { src = wo; dst = owo; i = idx - XC_F4 - WQ_F4; }
    float4 v = src[i];
    __half2 lo = __floats2half2_rn(v.x, v.y);
    __half2 hi = __floats2half2_rn(v.z, v.w);
    dst[i] = make_uint2(*(unsigned*)&lo, *(unsigned*)&hi);
}

// ---------------------------------------------------------------------------
// fp16 GEMM: C[m][n] = sum_k A[m][k]*B[n][k] (A:[M,K], B:[N,K] fp16).
// 128x128 block tile, K-tile 64 halves (4 k16 steps per barrier), 256 threads
// (8 warps, 64x32 warp tiles), 3-stage cp.async pipeline, 2 CTAs/SM.
// MODE 0: fp32 out -> C0.
// MODE 1: cols<2048 -> fp16 C0 (Q|K, stride 2048); cols>=2048 -> V^T fp16 C1.
// ---------------------------------------------------------------------------
#define NSTAGE 3
#define GSTR 36                 // u32 per smem row (32 data + 4 pad)
#define GTILE (128 * GSTR)
#define SMEM_GEMM (2 * NSTAGE * GTILE * 4)   // 110592 B

template <int MODE>
__global__ __launch_bounds__(256, 2)
void gemm_h(const __half* __restrict__ A, const __half* __restrict__ B,
            void* __restrict__ C0, void* __restrict__ C1, int M, int N, int K) {
    extern __shared__ unsigned smg[];
    unsigned* Abuf = smg;
    unsigned* Bbuf = smg + NSTAGE * GTILE;

    const int t    = threadIdx.x;
    const int lane = t & 31;
    const int w    = t >> 5;
    const int gid  = lane >> 2;
    const int tig  = lane & 3;
    const int wm   = w & 1;
    const int wn   = w >> 1;
    const int m0   = blockIdx.y * 128;
    const int n0   = blockIdx.x * 128;

    float acc[4][4][4];
#pragma unroll
    for (int i = 0; i < 4; i++)
#pragma unroll
        for (int j = 0; j < 4; j++)
#pragma unroll
            for (int e = 0; e < 4; e++) acc[i][j][e] = 0.f;

    const int nkt = K / 64;

    // one K-tile (64 halves): 128 rows x 8 chunks(16B) per operand
    auto issue = [&](int stage, int kt) {
        unsigned* as = Abuf + stage * GTILE;
        unsigned* bs = Bbuf + stage * GTILE;
        const __half* Ag = A + (size_t)m0 * K + kt * 64;
        const __half* Bg = B + (size_t)n0 * K + kt * 64;
#pragma unroll
        for (int i = 0; i < 4; i++) {
            const int c = t + i * 256;           // 0..1023
            const int row = c >> 3, cc = c & 7;
            cp_async16(&as[row * GSTR + cc * 4], Ag + (size_t)row * K + cc * 8);
            cp_async16(&bs[row * GSTR + cc * 4], Bg + (size_t)row * K + cc * 8);
        }
    };

    issue(0, 0); CP_COMMIT();
    issue(1, 1); CP_COMMIT();

    int stage = 0;
    for (int kt = 0; kt < nkt; kt++) {
        if (kt + 1 < nkt) { CP_WAIT1(); } else { CP_WAIT0(); }
        __syncthreads();          // tile kt ready

        if (kt + 2 < nkt) {
            int ns = stage + 2; if (ns >= NSTAGE) ns -= NSTAGE;
            issue(ns, kt + 2);
            CP_COMMIT();
        }

        const unsigned* As = Abuf + stage * GTILE;
        const unsigned* Bs = Bbuf + stage * GTILE;
        const int am = wm * 64;
        const int bn = wn * 32;
#pragma unroll
        for (int s = 0; s < 4; s++) {           // four k16 steps per tile
            const int kk = s * 8;
            unsigned av[4][4];
#pragma unroll
            for (int mi = 0; mi < 4; mi++) {
                const int r  = (am + 16 * mi + gid) * GSTR;
                const int r8 = r + 8 * GSTR;
                av[mi][0] = As[r + kk + tig];
                av[mi][1] = As[r8 + kk + tig];
                av[mi][2] = As[r + kk + tig + 4];
                av[mi][3] = As[r8 + kk + tig + 4];
            }
            unsigned bv[4][2];
#pragma unroll
            for (int nj = 0; nj < 4; nj++) {
                const int r = (bn + 8 * nj + gid) * GSTR;
                bv[nj][0] = Bs[r + kk + tig];
                bv[nj][1] = Bs[r + kk + tig + 4];
            }
#pragma unroll
            for (int mi = 0; mi < 4; mi++)
#pragma unroll
                for (int nj = 0; nj < 4; nj++)
                    mma_f16(acc[mi][nj], av[mi], bv[nj][0], bv[nj][1]);
        }
        __syncthreads();          // done reading stage before refill

        stage++; if (stage >= NSTAGE) stage -= NSTAGE;
    }

    // epilogue
#pragma unroll
    for (int mi = 0; mi < 4; mi++) {
        const int r = m0 + wm * 64 + 16 * mi + gid;
#pragma unroll
        for (int nj = 0; nj < 4; nj++) {
            const int c = n0 + wn * 32 + 8 * nj + 2 * tig;
            if (MODE == 0) {
                float* C = (float*)C0;
                *(float2*)(C + (size_t)r * N + c) =
                    make_float2(acc[mi][nj][0], acc[mi][nj][1]);
                *(float2*)(C + (size_t)(r + 8) * N + c) =
                    make_float2(acc[mi][nj][2], acc[mi][nj][3]);
            } else {
                if (n0 < 2 * D_MODEL) {   // Q|K -> fp16, stride 2048
                    __half2* C = (__half2*)C0;
                    C[((size_t)r * 2048 + c) >> 1] =
                        __floats2half2_rn(acc[mi][nj][0], acc[mi][nj][1]);
                    C[((size_t)(r + 8) * 2048 + c) >> 1] =
                        __floats2half2_rn(acc[mi][nj][2], acc[mi][nj][3]);
                } else {                  // V -> transposed fp16: vt[(b*1024+d)][s]
                    __half* VT = (__half*)C1;
                    const int dg = c - 2 * D_MODEL;          // global d (0..1023)
                    const size_t base =
                        ((size_t)(r >> 11) * D_MODEL + dg) * SEQ + (r & 2047);
                    VT[base]            = __float2half_rn(acc[mi][nj][0]);
                    VT[base + SEQ]      = __float2half_rn(acc[mi][nj][1]);
                    VT[base + 8]        = __float2half_rn(acc[mi][nj][2]);
                    VT[base + SEQ + 8]  = __float2half_rn(acc[mi][nj][3]);
                }
            }
        }
    }
}

// ---------------------------------------------------------------------------
// Causal flash attention, all-fp16 mma (S and PV), P register-resident.
// 64-query tiles, 128 threads, double-buffered cp.async K/V^T.
// smem: K [2][64][36 u32], V^T [2][64 d][36 u32], Q staging [64][36 u32].
// ---------------------------------------------------------------------------
#define AKS 36
#define AKS_ELEMS (64 * AKS)
#define AVS 36
#define AVS_ELEMS (64 * AVS)
#define AQS 36
#define SMEM_ATTN ((2 * AKS_ELEMS + 2 * AVS_ELEMS + 64 * AQS) * 4)   // 46080 B

__global__ __launch_bounds__(128)
void attn_h(const __half* __restrict__ qk, const __half* __restrict__ vt,
            __half* __restrict__ out) {
    extern __shared__ unsigned sma[];
    unsigned* KsB = sma;                                 // [2][64][AKS]
    unsigned* VsB = sma + 2 * AKS_ELEMS;                 // [2][64 d][AVS]
    unsigned* Qs  = sma + 2 * AKS_ELEMS + 2 * AVS_ELEMS; // [64][AQS]

    const int qt   = gridDim.x - 1 - blockIdx.x;      // heavy tiles first
    const int h    = blockIdx.y;
    const int b    = blockIdx.z;
    const int t    = threadIdx.x;
    const int lane = t & 31;
    const int w    = t >> 5;
    const int gid  = lane >> 2;
    const int tig  = lane & 3;
    const int q0   = qt * 64;

    const __half* kbase  = qk + (size_t)(b * SEQ) * 2048 + D_MODEL + h * HD;
    const __half* vtbase = vt + ((size_t)b * D_MODEL + h * HD) * SEQ;

    // K/V^T tile loader into buffer nb for key tile jt
    auto load_kv = [&](int nb, int jt) {
        const __half* kp = kbase + (size_t)jt * 64 * 2048;
        const __half* vp = vtbase + jt * 64;              // col offset s0
#pragma unroll
        for (int i = 0; i < 4; i++) {       // K: 64 rows x 8 chunks
            const int c = t + i * 128;
            const int row = c >> 3, cc = c & 7;
            cp_async16(&KsB[nb * AKS_ELEMS + row * AKS + cc * 4],
                       kp + (size_t)row * 2048 + cc * 8);
        }
#pragma unroll
        for (int i = 0; i < 4; i++) {       // V^T: 64 d-rows x 8 chunks
            const int c = t + i * 128;
            const int row = c >> 3, cc = c & 7;
            cp_async16(&VsB[nb * AVS_ELEMS + row * AVS + cc * 4],
                       vp + (size_t)row * SEQ + cc * 8);
        }
    };

    // prologue: Q tile + K/V tile 0
    {
        const __half* qp = qk + (size_t)(b * SEQ + q0) * 2048 + h * HD;
#pragma unroll
        for (int i = 0; i < 4; i++) {
            const int c = t + i * 128;
            const int row = c >> 3, cc = c & 7;
            cp_async16(&Qs[row * AQS + cc * 4], qp + (size_t)row * 2048 + cc * 8);
        }
        load_kv(0, 0);
    }
    CP_COMMIT();
    CP_WAIT0();
    __syncthreads();

    // Q fragments -> registers, scaled by 0.125 (exact in fp16)
    unsigned qf[4][4];
    {
        const __half2 sc = __float2half2_rn(0.125f);
        const int r0 = (16 * w + gid) * AQS;
        const int r1 = (16 * w + gid + 8) * AQS;
#pragma unroll
        for (int s = 0; s < 4; s++) {
            unsigned u0 = Qs[r0 + 8 * s + tig];
            unsigned u1 = Qs[r1 + 8 * s + tig];
            unsigned u2 = Qs[r0 + 8 * s + tig + 4];
            unsigned u3 = Qs[r1 + 8 * s + tig + 4];
            __half2 h0 = __hmul2(*(__half2*)&u0, sc);
            __half2 h1 = __hmul2(*(__half2*)&u1, sc);
            __half2 h2 = __hmul2(*(__half2*)&u2, sc);
            __half2 h3 = __hmul2(*(__half2*)&u3, sc);
            qf[s][0] = *(unsigned*)&h0;
            qf[s][1] = *(unsigned*)&h1;
            qf[s][2] = *(unsigned*)&h2;
            qf[s][3] = *(unsigned*)&h3;
        }
    }

    float o[8][4];
#pragma unroll
    for (int j = 0; j < 8; j++)
#pragma unroll
        for (int e = 0; e < 4; e++) o[j][e] = 0.f;
    float m0 = -1e30f, m1 = -1e30f, l0 = 0.f, l1 = 0.f;

    const int row0 = q0 + 16 * w + gid;

    for (int jt = 0; jt <= qt; jt++) {
        const int cur = jt & 1;
        if (jt + 1 <= qt) {
            load_kv(cur ^ 1, jt + 1);
            CP_COMMIT();
            CP_WAIT1();
        } else {
            CP_WAIT0();
        }
        __syncthreads();

        const unsigned* Ks = KsB + cur * AKS_ELEMS;
        const unsigned* Vs = VsB + cur * AVS_ELEMS;
        const int k0 = jt * 64;

        // S = Q K^T (fp16, 4 k16-steps)
        float sacc[8][4];
#pragma unroll
        for (int j = 0; j < 8; j++)
#pragma unroll
            for (int e = 0; e < 4; e++) sacc[j][e] = 0.f;

#pragma unroll
        for (int s = 0; s < 4; s++) {
#pragma unroll
            for (int j = 0; j < 8; j++) {
                const int kr = (8 * j + gid) * AKS + 8 * s + tig;
                mma_f16(sacc[j], qf[s], Ks[kr], Ks[kr + 4]);
            }
        }

        // mask + row max
        float mt0 = -1e30f, mt1 = -1e30f;
#pragma unroll
        for (int j = 0; j < 8; j++) {
            const int cb = k0 + 8 * j + 2 * tig;
            if (jt == qt) {
                if (cb     > row0)     sacc[j][0] = -1e30f;
                if (cb + 1 > row0)     sacc[j][1] = -1e30f;
                if (cb     > row0 + 8) sacc[j][2] = -1e30f;
                if (cb + 1 > row0 + 8) sacc[j][3] = -1e30f;
            }
            mt0 = fmaxf(mt0, fmaxf(sacc[j][0], sacc[j][1]));
            mt1 = fmaxf(mt1, fmaxf(sacc[j][2], sacc[j][3]));
        }
        mt0 = fmaxf(mt0, __shfl_xor_sync(0xffffffffu, mt0, 1));
        mt0 = fmaxf(mt0, __shfl_xor_sync(0xffffffffu, mt0, 2));
        mt1 = fmaxf(mt1, __shfl_xor_sync(0xffffffffu, mt1, 1));
        mt1 = fmaxf(mt1, __shfl_xor_sync(0xffffffffu, mt1, 2));

        const float mn0 = fmaxf(m0, mt0);
        const float mn1 = fmaxf(m1, mt1);
        const float al0 = __expf(m0 - mn0);
        const float al1 = __expf(m1 - mn1);
        m0 = mn0; m1 = mn1;

        // P = exp(S - m): pack fp16 A-fragments entirely in registers.
        // k16-chunk m covers s cols [16m,16m+16): a0,a1 <- j=2m; a2,a3 <- j=2m+1
        unsigned pf[4][4];
        float ls0 = 0.f, ls1 = 0.f;
#pragma unroll
        for (int j = 0; j < 8; j++) {
            float p00 = __expf(sacc[j][0] - mn0);
            float p01 = __expf(sacc[j][1] - mn0);
            float p10 = __expf(sacc[j][2] - mn1);
            float p11 = __expf(sacc[j][3] - mn1);
            ls0 += p00 + p01;
            ls1 += p10 + p11;
            __half2 lo = __floats2half2_rn(p00, p01);
            __half2 hi = __floats2half2_rn(p10, p11);
            const int m = j >> 1;
            const int off = (j & 1) << 1;   // 0 -> a0/a1, 1 -> a2/a3
            pf[m][off]     = *(unsigned*)&lo;
            pf[m][off + 1] = *(unsigned*)&hi;
        }
        ls0 += __shfl_xor_sync(0xffffffffu, ls0, 1);
        ls0 += __shfl_xor_sync(0xffffffffu, ls0, 2);
        ls1 += __shfl_xor_sync(0xffffffffu, ls1, 1);
        ls1 += __shfl_xor_sync(0xffffffffu, ls1, 2);
        l0 = l0 * al0 + ls0;
        l1 = l1 * al1 + ls1;

#pragma unroll
        for (int j = 0; j < 8; j++) {
            o[j][0] *= al0; o[j][1] *= al0;
            o[j][2] *= al1; o[j][3] *= al1;
        }

        // O += P V (fp16). B frag from V^T smem: b0 = V[s=16m+2tig..][d=8j+gid]
#pragma unroll
        for (int m = 0; m < 4; m++) {
#pragma unroll
            for (int j = 0; j < 8; j++) {
                const int vb = (8 * j + gid) * AVS + 8 * m + tig;
                mma_f16(o[j], pf[m], Vs[vb], Vs[vb + 4]);
            }
        }
        __syncthreads();    // done reading cur before overwrite
    }

    // epilogue -> fp16 for the output projection
    const float i0 = 1.f / l0;
    const float i1 = 1.f / l1;
    __half2* op0 = (__half2*)(out + (size_t)(b * SEQ + row0) * D_MODEL + h * HD);
    __half2* op1 = (__half2*)(out + (size_t)(b * SEQ + row0 + 8) * D_MODEL + h * HD);
#pragma unroll
    for (int j = 0; j < 8; j++) {
        const int c = (8 * j + 2 * tig) >> 1;
        op0[c] = __floats2half2_rn(o[j][0] * i0, o[j][1] * i0);
        op1[c] = __floats2half2_rn(o[j][2] * i1, o[j][3] * i1);
    }
}

extern "C" void kernel_launch(void* const* d_in, const int* in_sizes, int n_in,
                              void* d_out, int out_size) {
    const float* x     = (const float*)d_in[0];
    const float* w_qkv = (const float*)d_in[1];
    const float* w_o   = (const float*)d_in[2];
    float* out         = (float*)d_out;

    __half *qkh, *vt, *ao, *xh, *wqh, *woh;
    cudaGetSymbolAddress((void**)&qkh, g_qkh);
    cudaGetSymbolAddress((void**)&vt,  g_vt);
    cudaGetSymbolAddress((void**)&ao,  g_ao);
    cudaGetSymbolAddress((void**)&xh,  g_xh);
    cudaGetSymbolAddress((void**)&wqh, g_wqh);
    cudaGetSymbolAddress((void**)&woh, g_woh);

    static bool attr_set = false;
    if (!attr_set) {
        cudaFuncSetAttribute(gemm_h<0>, cudaFuncAttributeMaxDynamicSharedMemorySize, SMEM_GEMM);
        cudaFuncSetAttribute(gemm_h<1>, cudaFuncAttributeMaxDynamicSharedMemorySize, SMEM_GEMM);
        cudaFuncSetAttribute(attn_h, cudaFuncAttributeMaxDynamicSharedMemorySize, SMEM_ATTN);
        attr_set = true;
    }

    // 0) fp32 -> fp16 pre-pass
    conv_h<<<CONV_BLOCKS, 256>>>((const float4*)x, (const float4*)w_qkv, (const float4*)w_o,
                                 (uint2*)xh, (uint2*)wqh, (uint2*)woh);

    // 1) QKV projection (fp16 mma): Q|K -> fp16, V -> transposed fp16
    gemm_h<1><<<dim3(QKV_W / 128, M_TOT / 128), 256, SMEM_GEMM>>>(
        xh, wqh, qkh, vt, M_TOT, QKV_W, D_MODEL);

    // 2) causal attention -> fp16
    attn_h<<<dim3(SEQ / 64, NHEAD, BATCH), 128, SMEM_ATTN>>>(qkh, vt, ao);

    // 3) output projection (fp16 mma) -> fp32
    gemm_h<0><<<dim3(D_MODEL / 128, M_TOT / 128), 256, SMEM_GEMM>>>(
        ao, woh, out, nullptr, M_TOT, D_MODEL, D_MODEL);
}

// round 11
// speedup vs baseline: 2.0042x; 1.0456x over previous
#include <cuda_runtime.h>
#include <cuda_fp16.h>
#include <cstdint>

#define D_MODEL 1024
#define NHEAD   16
#define HD      64
#define SEQ     2048
#define BATCH   2
#define M_TOT   (BATCH * SEQ)   // 4096
#define QKV_W   (3 * D_MODEL)   // 3072

// Scratch (no cudaMalloc allowed).
__device__ __half g_qkh[(size_t)M_TOT * 2 * D_MODEL];  // Q|K fp16 [4096][2048]
__device__ __half g_vt [(size_t)M_TOT * D_MODEL];      // V^T fp16 [(b*1024+d)][2048 s]
__device__ __half g_ao [(size_t)M_TOT * D_MODEL];      // attn out fp16
__device__ __half g_xh [(size_t)M_TOT * D_MODEL];      // x -> fp16
__device__ __half g_wqh[(size_t)QKV_W * D_MODEL];      // w_qkv -> fp16
__device__ __half g_woh[(size_t)D_MODEL * D_MODEL];    // w_o -> fp16

// fp16 mma: D(fp32) += A(f16 m16k16 row) x B(f16 k16n8 col)
__device__ __forceinline__ void mma_f16(float* c, const unsigned* a,
                                        unsigned b0, unsigned b1) {
    asm volatile(
        "mma.sync.aligned.m16n8k16.row.col.f32.f16.f16.f32 "
        "{%0,%1,%2,%3},{%4,%5,%6,%7},{%8,%9},{%0,%1,%2,%3};\n"
        : "+f"(c[0]), "+f"(c[1]), "+f"(c[2]), "+f"(c[3])
        : "r"(a[0]), "r"(a[1]), "r"(a[2]), "r"(a[3]), "r"(b0), "r"(b1));
}

__device__ __forceinline__ void ldsm4(unsigned& r0, unsigned& r1,
                                      unsigned& r2, unsigned& r3, unsigned addr) {
    asm volatile("ldmatrix.sync.aligned.m8n8.x4.shared.b16 {%0,%1,%2,%3}, [%4];"
                 : "=r"(r0), "=r"(r1), "=r"(r2), "=r"(r3) : "r"(addr));
}

__device__ __forceinline__ void cp_async16(void* smem_dst, const void* gmem_src) {
    unsigned s = (unsigned)__cvta_generic_to_shared(smem_dst);
    asm volatile("cp.async.cg.shared.global [%0], [%1], 16;\n" :: "r"(s), "l"(gmem_src));
}
#define CP_COMMIT() asm volatile("cp.async.commit_group;\n" ::: "memory")
#define CP_WAIT1()  asm volatile("cp.async.wait_group 1;\n" ::: "memory")
#define CP_WAIT0()  asm volatile("cp.async.wait_group 0;\n" ::: "memory")

// ---------------------------------------------------------------------------
// fp32 -> fp16 pre-pass (x, w_qkv, w_o)
// ---------------------------------------------------------------------------
#define XC_F4 ((M_TOT * D_MODEL) / 4)
#define WQ_F4 ((QKV_W * D_MODEL) / 4)
#define WO_F4 ((D_MODEL * D_MODEL) / 4)
#define CONV_BLOCKS ((XC_F4 + WQ_F4 + WO_F4) / 256)

__global__ void conv_h(const float4* __restrict__ x,
                       const float4* __restrict__ wq,
                       const float4* __restrict__ wo,
                       uint2* __restrict__ ox,
                       uint2* __restrict__ owq,
                       uint2* __restrict__ owo) {
    const int idx = blockIdx.x * 256 + threadIdx.x;
    const float4* src;
    uint2* dst;
    int i;
    if (idx < XC_F4)                { src = x;  dst = ox;  i = idx; }
    else if (idx < XC_F4 + WQ_F4)   { src = wq; dst = owq; i = idx - XC_F4; }
    else                            { src = wo; dst = owo; i = idx - XC_F4 - WQ_F4; }
    float4 v = src[i];
    __half2 lo = __floats2half2_rn(v.x, v.y);
    __half2 hi = __floats2half2_rn(v.z, v.w);
    dst[i] = make_uint2(*(unsigned*)&lo, *(unsigned*)&hi);
}

// ---------------------------------------------------------------------------
// fp16 GEMM with ldmatrix fragment loads.
// 128x128 block tile, K-tile 64 halves, 256 threads (8 warps, 64x32 tiles),
// 3-stage cp.async pipeline, 2 CTAs/SM.
// MODE 0: fp32 out -> C0.
// MODE 1: cols<2048 -> fp16 C0 (Q|K, stride 2048); cols>=2048 -> V^T fp16 C1.
// ---------------------------------------------------------------------------
#define NSTAGE 3
#define GSTR 36                 // u32 per smem row (32 data + 4 pad)
#define GTILE (128 * GSTR)
#define SMEM_GEMM (2 * NSTAGE * GTILE * 4)   // 110592 B

template <int MODE>
__global__ __launch_bounds__(256, 2)
void gemm_h(const __half* __restrict__ A, const __half* __restrict__ B,
            void* __restrict__ C0, void* __restrict__ C1, int M, int N, int K) {
    extern __shared__ unsigned smg[];
    unsigned* Abuf = smg;
    unsigned* Bbuf = smg + NSTAGE * GTILE;
    const unsigned smb = (unsigned)__cvta_generic_to_shared(smg);

    const int t    = threadIdx.x;
    const int lane = t & 31;
    const int w    = t >> 5;
    const int gid  = lane >> 2;
    const int tig  = lane & 3;
    const int wm   = w & 1;
    const int wn   = w >> 1;
    const int m0   = blockIdx.y * 128;
    const int n0   = blockIdx.x * 128;

    // ldmatrix per-lane addressing
    const int li  = lane & 7;
    const int q8  = (lane >> 3) & 1;
    const int q16 = lane >> 4;
    // A x4: m0=(rows base..+7, kcol kk), m1=(+8, kk), m2=(base, kk+4), m3=(+8, kk+4)
    const unsigned aLane = ((unsigned)((wm * 64 + q8 * 8 + li) * GSTR + q16 * 4)) * 4;
    // B x4 (nj pair p): m0=(bn+16p, kk), m1=(bn+16p, kk+4), m2=(+8, kk), m3=(+8, kk+4)
    const unsigned bLane = ((unsigned)((wn * 32 + q16 * 8 + li) * GSTR + q8 * 4)) * 4;

    float acc[4][4][4];
#pragma unroll
    for (int i = 0; i < 4; i++)
#pragma unroll
        for (int j = 0; j < 4; j++)
#pragma unroll
            for (int e = 0; e < 4; e++) acc[i][j][e] = 0.f;

    const int nkt = K / 64;

    auto issue = [&](int stage, int kt) {
        unsigned* as = Abuf + stage * GTILE;
        unsigned* bs = Bbuf + stage * GTILE;
        const __half* Ag = A + (size_t)m0 * K + kt * 64;
        const __half* Bg = B + (size_t)n0 * K + kt * 64;
#pragma unroll
        for (int i = 0; i < 4; i++) {
            const int c = t + i * 256;           // 0..1023
            const int row = c >> 3, cc = c & 7;
            cp_async16(&as[row * GSTR + cc * 4], Ag + (size_t)row * K + cc * 8);
            cp_async16(&bs[row * GSTR + cc * 4], Bg + (size_t)row * K + cc * 8);
        }
    };

    issue(0, 0); CP_COMMIT();
    issue(1, 1); CP_COMMIT();

    int stage = 0;
    for (int kt = 0; kt < nkt; kt++) {
        if (kt + 1 < nkt) { CP_WAIT1(); } else { CP_WAIT0(); }
        __syncthreads();

        if (kt + 2 < nkt) {
            int ns = stage + 2; if (ns >= NSTAGE) ns -= NSTAGE;
            issue(ns, kt + 2);
            CP_COMMIT();
        }

        const unsigned aBase = smb + (unsigned)(stage * GTILE) * 4 + aLane;
        const unsigned bBase = smb + (unsigned)((NSTAGE + stage) * GTILE) * 4 + bLane;
#pragma unroll
        for (int s = 0; s < 4; s++) {
            unsigned av[4][4];
#pragma unroll
            for (int mi = 0; mi < 4; mi++)
                ldsm4(av[mi][0], av[mi][1], av[mi][2], av[mi][3],
                      aBase + mi * (16 * GSTR * 4) + s * 32);
            unsigned bv[4][2];
            ldsm4(bv[0][0], bv[0][1], bv[1][0], bv[1][1], bBase + s * 32);
            ldsm4(bv[2][0], bv[2][1], bv[3][0], bv[3][1],
                  bBase + 16 * GSTR * 4 + s * 32);
#pragma unroll
            for (int mi = 0; mi < 4; mi++)
#pragma unroll
                for (int nj = 0; nj < 4; nj++)
                    mma_f16(acc[mi][nj], av[mi], bv[nj][0], bv[nj][1]);
        }
        __syncthreads();

        stage++; if (stage >= NSTAGE) stage -= NSTAGE;
    }

    // epilogue
#pragma unroll
    for (int mi = 0; mi < 4; mi++) {
        const int r = m0 + wm * 64 + 16 * mi + gid;
#pragma unroll
        for (int nj = 0; nj < 4; nj++) {
            const int c = n0 + wn * 32 + 8 * nj + 2 * tig;
            if (MODE == 0) {
                float* C = (float*)C0;
                *(float2*)(C + (size_t)r * N + c) =
                    make_float2(acc[mi][nj][0], acc[mi][nj][1]);
                *(float2*)(C + (size_t)(r + 8) * N + c) =
                    make_float2(acc[mi][nj][2], acc[mi][nj][3]);
            } else {
                if (n0 < 2 * D_MODEL) {   // Q|K -> fp16, stride 2048
                    __half2* C = (__half2*)C0;
                    C[((size_t)r * 2048 + c) >> 1] =
                        __floats2half2_rn(acc[mi][nj][0], acc[mi][nj][1]);
                    C[((size_t)(r + 8) * 2048 + c) >> 1] =
                        __floats2half2_rn(acc[mi][nj][2], acc[mi][nj][3]);
                } else {                  // V -> transposed fp16: vt[(b*1024+d)][s]
                    __half* VT = (__half*)C1;
                    const int dg = c - 2 * D_MODEL;
                    const size_t base =
                        ((size_t)(r >> 11) * D_MODEL + dg) * SEQ + (r & 2047);
                    VT[base]            = __float2half_rn(acc[mi][nj][0]);
                    VT[base + SEQ]      = __float2half_rn(acc[mi][nj][1]);
                    VT[base + 8]        = __float2half_rn(acc[mi][nj][2]);
                    VT[base + SEQ + 8]  = __float2half_rn(acc[mi][nj][3]);
                }
            }
        }
    }
}

// ---------------------------------------------------------------------------
// Causal flash attention, all-fp16 mma, register-resident P, ldmatrix frags.
// 128-query tiles, 256 threads (8 warps x 16 rows), double-buffered K/V^T.
// Key tiles 64 wide: jt_max = 2qt+1, mask only on jt >= 2qt.
// ---------------------------------------------------------------------------
#define AKS 36
#define AKS_ELEMS (64 * AKS)
#define AVS 36
#define AVS_ELEMS (64 * AVS)
#define AQS 36
#define QROWS 128
#define SMEM_ATTN ((2 * AKS_ELEMS + 2 * AVS_ELEMS + QROWS * AQS) * 4)   // 55296 B

__global__ __launch_bounds__(256)
void attn_h(const __half* __restrict__ qk, const __half* __restrict__ vt,
            __half* __restrict__ out) {
    extern __shared__ unsigned sma[];
    unsigned* KsB = sma;                                 // [2][64][AKS]
    unsigned* VsB = sma + 2 * AKS_ELEMS;                 // [2][64 d][AVS]
    unsigned* Qs  = sma + 2 * AKS_ELEMS + 2 * AVS_ELEMS; // [128][AQS]
    const unsigned smb = (unsigned)__cvta_generic_to_shared(sma);

    const int qt   = gridDim.x - 1 - blockIdx.x;      // heavy tiles first
    const int h    = blockIdx.y;
    const int b    = blockIdx.z;
    const int t    = threadIdx.x;
    const int lane = t & 31;
    const int w    = t >> 5;        // 0..7
    const int gid  = lane >> 2;
    const int tig  = lane & 3;
    const int q0   = qt * QROWS;

    const int li  = lane & 7;
    const int q8  = (lane >> 3) & 1;
    const int q16 = lane >> 4;
    // B-style x4 lane address (rows = 16p + q16*8 + li, col add = q8*4 u32)
    const unsigned kLane = ((unsigned)((q16 * 8 + li) * AKS + q8 * 4)) * 4;
    const unsigned vLane = ((unsigned)((q16 * 8 + li) * AVS + q8 * 4)) * 4;

    const __half* kbase  = qk + (size_t)(b * SEQ) * 2048 + D_MODEL + h * HD;
    const __half* vtbase = vt + ((size_t)b * D_MODEL + h * HD) * SEQ;

    auto load_kv = [&](int nb, int jt) {
        const __half* kp = kbase + (size_t)jt * 64 * 2048;
        const __half* vp = vtbase + jt * 64;
#pragma unroll
        for (int i = 0; i < 2; i++) {       // K: 64 rows x 8 chunks = 512
            const int c = t + i * 256;
            const int row = c >> 3, cc = c & 7;
            cp_async16(&KsB[nb * AKS_ELEMS + row * AKS + cc * 4],
                       kp + (size_t)row * 2048 + cc * 8);
        }
#pragma unroll
        for (int i = 0; i < 2; i++) {       // V^T: 64 d-rows x 8 chunks = 512
            const int c = t + i * 256;
            const int row = c >> 3, cc = c & 7;
            cp_async16(&VsB[nb * AVS_ELEMS + row * AVS + cc * 4],
                       vp + (size_t)row * SEQ + cc * 8);
        }
    };

    // prologue: Q tile (128 rows) + K/V tile 0
    {
        const __half* qp = qk + (size_t)(b * SEQ + q0) * 2048 + h * HD;
#pragma unroll
        for (int i = 0; i < 4; i++) {       // Q: 128 rows x 8 chunks = 1024
            const int c = t + i * 256;
            const int row = c >> 3, cc = c & 7;
            cp_async16(&Qs[row * AQS + cc * 4], qp + (size_t)row * 2048 + cc * 8);
        }
        load_kv(0, 0);
    }
    CP_COMMIT();
    CP_WAIT0();
    __syncthreads();

    // Q fragments -> registers, scaled by 0.125 (exact in fp16)
    unsigned qf[4][4];
    {
        const __half2 sc = __float2half2_rn(0.125f);
        const int r0 = (16 * w + gid) * AQS;
        const int r1 = (16 * w + gid + 8) * AQS;
#pragma unroll
        for (int s = 0; s < 4; s++) {
            unsigned u0 = Qs[r0 + 8 * s + tig];
            unsigned u1 = Qs[r1 + 8 * s + tig];
            unsigned u2 = Qs[r0 + 8 * s + tig + 4];
            unsigned u3 = Qs[r1 + 8 * s + tig + 4];
            __half2 h0 = __hmul2(*(__half2*)&u0, sc);
            __half2 h1 = __hmul2(*(__half2*)&u1, sc);
            __half2 h2 = __hmul2(*(__half2*)&u2, sc);
            __half2 h3 = __hmul2(*(__half2*)&u3, sc);
            qf[s][0] = *(unsigned*)&h0;
            qf[s][1] = *(unsigned*)&h1;
            qf[s][2] = *(unsigned*)&h2;
            qf[s][3] = *(unsigned*)&h3;
        }
    }

    float o[8][4];
#pragma unroll
    for (int j = 0; j < 8; j++)
#pragma unroll
        for (int e = 0; e < 4; e++) o[j][e] = 0.f;
    float m0 = -1e30f, m1 = -1e30f, l0 = 0.f, l1 = 0.f;

    const int row0 = q0 + 16 * w + gid;
    const int jt_max = 2 * qt + 1;

    for (int jt = 0; jt <= jt_max; jt++) {
        const int cur = jt & 1;
        if (jt + 1 <= jt_max) {
            load_kv(cur ^ 1, jt + 1);
            CP_COMMIT();
            CP_WAIT1();
        } else {
            CP_WAIT0();
        }
        __syncthreads();

        const unsigned kBase = smb + (unsigned)(cur * AKS_ELEMS) * 4 + kLane;
        const unsigned vBase = smb + (unsigned)((2 * AKS_ELEMS) + cur * AVS_ELEMS) * 4 + vLane;
        const int k0 = jt * 64;

        // S = Q K^T (fp16, 4 k16-steps, K frags via ldmatrix x4 per j-pair)
        float sacc[8][4];
#pragma unroll
        for (int j = 0; j < 8; j++)
#pragma unroll
            for (int e = 0; e < 4; e++) sacc[j][e] = 0.f;

#pragma unroll
        for (int s = 0; s < 4; s++) {
#pragma unroll
            for (int p = 0; p < 4; p++) {
                unsigned k0r, k1r, k2r, k3r;
                ldsm4(k0r, k1r, k2r, k3r, kBase + p * (16 * AKS * 4) + s * 32);
                mma_f16(sacc[2 * p],     qf[s], k0r, k1r);
                mma_f16(sacc[2 * p + 1], qf[s], k2r, k3r);
            }
        }

        // mask (only last two tiles cross the diagonal) + row max
        const bool need_mask = (jt >= 2 * qt);
        float mt0 = -1e30f, mt1 = -1e30f;
#pragma unroll
        for (int j = 0; j < 8; j++) {
            const int cb = k0 + 8 * j + 2 * tig;
            if (need_mask) {
                if (cb     > row0)     sacc[j][0] = -1e30f;
                if (cb + 1 > row0)     sacc[j][1] = -1e30f;
                if (cb     > row0 + 8) sacc[j][2] = -1e30f;
                if (cb + 1 > row0 + 8) sacc[j][3] = -1e30f;
            }
            mt0 = fmaxf(mt0, fmaxf(sacc[j][0], sacc[j][1]));
            mt1 = fmaxf(mt1, fmaxf(sacc[j][2], sacc[j][3]));
        }
        mt0 = fmaxf(mt0, __shfl_xor_sync(0xffffffffu, mt0, 1));
        mt0 = fmaxf(mt0, __shfl_xor_sync(0xffffffffu, mt0, 2));
        mt1 = fmaxf(mt1, __shfl_xor_sync(0xffffffffu, mt1, 1));
        mt1 = fmaxf(mt1, __shfl_xor_sync(0xffffffffu, mt1, 2));

        const float mn0 = fmaxf(m0, mt0);
        const float mn1 = fmaxf(m1, mt1);
        const float al0 = __expf(m0 - mn0);
        const float al1 = __expf(m1 - mn1);
        m0 = mn0; m1 = mn1;

        // P = exp(S - m): pack fp16 A-fragments in registers
        unsigned pf[4][4];
        float ls0 = 0.f, ls1 = 0.f;
#pragma unroll
        for (int j = 0; j < 8; j++) {
            float p00 = __expf(sacc[j][0] - mn0);
            float p01 = __expf(sacc[j][1] - mn0);
            float p10 = __expf(sacc[j][2] - mn1);
            float p11 = __expf(sacc[j][3] - mn1);
            ls0 += p00 + p01;
            ls1 += p10 + p11;
            __half2 lo = __floats2half2_rn(p00, p01);
            __half2 hi = __floats2half2_rn(p10, p11);
            const int m = j >> 1;
            const int off = (j & 1) << 1;
            pf[m][off]     = *(unsigned*)&lo;
            pf[m][off + 1] = *(unsigned*)&hi;
        }
        ls0 += __shfl_xor_sync(0xffffffffu, ls0, 1);
        ls0 += __shfl_xor_sync(0xffffffffu, ls0, 2);
        ls1 += __shfl_xor_sync(0xffffffffu, ls1, 1);
        ls1 += __shfl_xor_sync(0xffffffffu, ls1, 2);
        l0 = l0 * al0 + ls0;
        l1 = l1 * al1 + ls1;

#pragma unroll
        for (int j = 0; j < 8; j++) {
            o[j][0] *= al0; o[j][1] *= al0;
            o[j][2] *= al1; o[j][3] *= al1;
        }

        // O += P V (fp16, V^T frags via ldmatrix x4 per j-pair)
#pragma unroll
        for (int m = 0; m < 4; m++) {
#pragma unroll
            for (int p = 0; p < 4; p++) {
                unsigned v0, v1, v2, v3;
                ldsm4(v0, v1, v2, v3, vBase + p * (16 * AVS * 4) + m * 32);
                mma_f16(o[2 * p],     pf[m], v0, v1);
                mma_f16(o[2 * p + 1], pf[m], v2, v3);
            }
        }
        __syncthreads();    // done reading cur before overwrite
    }

    // epilogue -> fp16 for the output projection
    const float i0 = 1.f / l0;
    const float i1 = 1.f / l1;
    __half2* op0 = (__half2*)(out + (size_t)(b * SEQ + row0) * D_MODEL + h * HD);
    __half2* op1 = (__half2*)(out + (size_t)(b * SEQ + row0 + 8) * D_MODEL + h * HD);
#pragma unroll
    for (int j = 0; j < 8; j++) {
        const int c = (8 * j + 2 * tig) >> 1;
        op0[c] = __floats2half2_rn(o[j][0] * i0, o[j][1] * i0);
        op1[c] = __floats2half2_rn(o[j][2] * i1, o[j][3] * i1);
    }
}

extern "C" void kernel_launch(void* const* d_in, const int* in_sizes, int n_in,
                              void* d_out, int out_size) {
    const float* x     = (const float*)d_in[0];
    const float* w_qkv = (const float*)d_in[1];
    const float* w_o   = (const float*)d_in[2];
    float* out         = (float*)d_out;

    __half *qkh, *vt, *ao, *xh, *wqh, *woh;
    cudaGetSymbolAddress((void**)&qkh, g_qkh);
    cudaGetSymbolAddress((void**)&vt,  g_vt);
    cudaGetSymbolAddress((void**)&ao,  g_ao);
    cudaGetSymbolAddress((void**)&xh,  g_xh);
    cudaGetSymbolAddress((void**)&wqh, g_wqh);
    cudaGetSymbolAddress((void**)&woh, g_woh);

    static bool attr_set = false;
    if (!attr_set) {
        cudaFuncSetAttribute(gemm_h<0>, cudaFuncAttributeMaxDynamicSharedMemorySize, SMEM_GEMM);
        cudaFuncSetAttribute(gemm_h<1>, cudaFuncAttributeMaxDynamicSharedMemorySize, SMEM_GEMM);
        cudaFuncSetAttribute(attn_h, cudaFuncAttributeMaxDynamicSharedMemorySize, SMEM_ATTN);
        attr_set = true;
    }

    // 0) fp32 -> fp16 pre-pass
    conv_h<<<CONV_BLOCKS, 256>>>((const float4*)x, (const float4*)w_qkv, (const float4*)w_o,
                                 (uint2*)xh, (uint2*)wqh, (uint2*)woh);

    // 1) QKV projection (fp16 mma): Q|K -> fp16, V -> transposed fp16
    gemm_h<1><<<dim3(QKV_W / 128, M_TOT / 128), 256, SMEM_GEMM>>>(
        xh, wqh, qkh, vt, M_TOT, QKV_W, D_MODEL);

    // 2) causal attention -> fp16
    attn_h<<<dim3(SEQ / QROWS, NHEAD, BATCH), 256, SMEM_ATTN>>>(qkh, vt, ao);

    // 3) output projection (fp16 mma) -> fp32
    gemm_h<0><<<dim3(D_MODEL / 128, M_TOT / 128), 256, SMEM_GEMM>>>(
        ao, woh, out, nullptr, M_TOT, D_MODEL, D_MODEL);
}

// round 12
// speedup vs baseline: 2.1046x; 1.0501x over previous
#include <cuda_runtime.h>
#include <cuda_fp16.h>
#include <cstdint>

#define D_MODEL 1024
#define NHEAD   16
#define HD      64
#define SEQ     2048
#define BATCH   2
#define M_TOT   (BATCH * SEQ)   // 4096
#define QKV_W   (3 * D_MODEL)   // 3072

// Scratch (no cudaMalloc allowed).
__device__ __half g_qkh[(size_t)M_TOT * 2 * D_MODEL];  // Q|K fp16 [4096][2048]
__device__ __half g_vt [(size_t)M_TOT * D_MODEL];      // V^T fp16 [(b*1024+d)][2048 s]
__device__ __half g_ao [(size_t)M_TOT * D_MODEL];      // attn out fp16
__device__ __half g_xh [(size_t)M_TOT * D_MODEL];      // x -> fp16
__device__ __half g_wqh[(size_t)QKV_W * D_MODEL];      // w_qkv -> fp16
__device__ __half g_woh[(size_t)D_MODEL * D_MODEL];    // w_o -> fp16

// fp16 mma: D(fp32) += A(f16 m16k16 row) x B(f16 k16n8 col)
__device__ __forceinline__ void mma_f16(float* c, const unsigned* a,
                                        unsigned b0, unsigned b1) {
    asm volatile(
        "mma.sync.aligned.m16n8k16.row.col.f32.f16.f16.f32 "
        "{%0,%1,%2,%3},{%4,%5,%6,%7},{%8,%9},{%0,%1,%2,%3};\n"
        : "+f"(c[0]), "+f"(c[1]), "+f"(c[2]), "+f"(c[3])
        : "r"(a[0]), "r"(a[1]), "r"(a[2]), "r"(a[3]), "r"(b0), "r"(b1));
}

__device__ __forceinline__ void ldsm4(unsigned& r0, unsigned& r1,
                                      unsigned& r2, unsigned& r3, unsigned addr) {
    asm volatile("ldmatrix.sync.aligned.m8n8.x4.shared.b16 {%0,%1,%2,%3}, [%4];"
                 : "=r"(r0), "=r"(r1), "=r"(r2), "=r"(r3) : "r"(addr));
}

__device__ __forceinline__ float fexp2(float x) {
    float r;
    asm("ex2.approx.ftz.f32 %0, %1;" : "=f"(r) : "f"(x));
    return r;
}

__device__ __forceinline__ void cp_async16(void* smem_dst, const void* gmem_src) {
    unsigned s = (unsigned)__cvta_generic_to_shared(smem_dst);
    asm volatile("cp.async.cg.shared.global [%0], [%1], 16;\n" :: "r"(s), "l"(gmem_src));
}
#define CP_COMMIT() asm volatile("cp.async.commit_group;\n" ::: "memory")
#define CP_WAIT1()  asm volatile("cp.async.wait_group 1;\n" ::: "memory")
#define CP_WAIT0()  asm volatile("cp.async.wait_group 0;\n" ::: "memory")

// ---------------------------------------------------------------------------
// fp32 -> fp16 pre-pass (x, w_qkv, w_o)
// ---------------------------------------------------------------------------
#define XC_F4 ((M_TOT * D_MODEL) / 4)
#define WQ_F4 ((QKV_W * D_MODEL) / 4)
#define WO_F4 ((D_MODEL * D_MODEL) / 4)
#define CONV_BLOCKS ((XC_F4 + WQ_F4 + WO_F4) / 256)

__global__ void conv_h(const float4* __restrict__ x,
                       const float4* __restrict__ wq,
                       const float4* __restrict__ wo,
                       uint2* __restrict__ ox,
                       uint2* __restrict__ owq,
                       uint2* __restrict__ owo) {
    const int idx = blockIdx.x * 256 + threadIdx.x;
    const float4* src;
    uint2* dst;
    int i;
    if (idx < XC_F4)                { src = x;  dst = ox;  i = idx; }
    else if (idx < XC_F4 + WQ_F4)   { src = wq; dst = owq; i = idx - XC_F4; }
    else                            { src = wo; dst = owo; i = idx - XC_F4 - WQ_F4; }
    float4 v = src[i];
    __half2 lo = __floats2half2_rn(v.x, v.y);
    __half2 hi = __floats2half2_rn(v.z, v.w);
    dst[i] = make_uint2(*(unsigned*)&lo, *(unsigned*)&hi);
}

// ---------------------------------------------------------------------------
// fp16 GEMM with ldmatrix fragment loads.
// 128x128 block tile, K-tile 64 halves, 256 threads (8 warps, 64x32 tiles),
// 3-stage cp.async pipeline with ONE __syncthreads per K-tile, 2 CTAs/SM.
// MODE 0: fp32 out -> C0.
// MODE 1: cols<2048 -> fp16 C0 (Q|K, stride 2048); cols>=2048 -> V^T fp16 C1.
// ---------------------------------------------------------------------------
#define NSTAGE 3
#define GSTR 36                 // u32 per smem row (32 data + 4 pad)
#define GTILE (128 * GSTR)
#define SMEM_GEMM (2 * NSTAGE * GTILE * 4)   // 110592 B

template <int MODE>
__global__ __launch_bounds__(256, 2)
void gemm_h(const __half* __restrict__ A, const __half* __restrict__ B,
            void* __restrict__ C0, void* __restrict__ C1, int M, int N, int K) {
    extern __shared__ unsigned smg[];
    unsigned* Abuf = smg;
    unsigned* Bbuf = smg + NSTAGE * GTILE;
    const unsigned smb = (unsigned)__cvta_generic_to_shared(smg);

    const int t    = threadIdx.x;
    const int lane = t & 31;
    const int w    = t >> 5;
    const int gid  = lane >> 2;
    const int tig  = lane & 3;
    const int wm   = w & 1;
    const int wn   = w >> 1;
    const int m0   = blockIdx.y * 128;
    const int n0   = blockIdx.x * 128;

    const int li  = lane & 7;
    const int q8  = (lane >> 3) & 1;
    const int q16 = lane >> 4;
    const unsigned aLane = ((unsigned)((wm * 64 + q8 * 8 + li) * GSTR + q16 * 4)) * 4;
    const unsigned bLane = ((unsigned)((wn * 32 + q16 * 8 + li) * GSTR + q8 * 4)) * 4;

    float acc[4][4][4];
#pragma unroll
    for (int i = 0; i < 4; i++)
#pragma unroll
        for (int j = 0; j < 4; j++)
#pragma unroll
            for (int e = 0; e < 4; e++) acc[i][j][e] = 0.f;

    const int nkt = K / 64;

    auto issue = [&](int stage, int kt) {
        unsigned* as = Abuf + stage * GTILE;
        unsigned* bs = Bbuf + stage * GTILE;
        const __half* Ag = A + (size_t)m0 * K + kt * 64;
        const __half* Bg = B + (size_t)n0 * K + kt * 64;
#pragma unroll
        for (int i = 0; i < 4; i++) {
            const int c = t + i * 256;           // 0..1023
            const int row = c >> 3, cc = c & 7;
            cp_async16(&as[row * GSTR + cc * 4], Ag + (size_t)row * K + cc * 8);
            cp_async16(&bs[row * GSTR + cc * 4], Bg + (size_t)row * K + cc * 8);
        }
    };

    issue(0, 0); CP_COMMIT();
    issue(1, 1); CP_COMMIT();

    int stage = 0;
    for (int kt = 0; kt < nkt; kt++) {
        if (kt + 1 < nkt) { CP_WAIT1(); } else { CP_WAIT0(); }
        __syncthreads();   // tile kt visible to all; all warps done with buf (kt-1)%3

        if (kt + 2 < nkt) {
            int ns = stage + 2; if (ns >= NSTAGE) ns -= NSTAGE;
            issue(ns, kt + 2);
            CP_COMMIT();
        }

        const unsigned aBase = smb + (unsigned)(stage * GTILE) * 4 + aLane;
        const unsigned bBase = smb + (unsigned)((NSTAGE + stage) * GTILE) * 4 + bLane;
#pragma unroll
        for (int s = 0; s < 4; s++) {
            unsigned av[4][4];
#pragma unroll
            for (int mi = 0; mi < 4; mi++)
                ldsm4(av[mi][0], av[mi][1], av[mi][2], av[mi][3],
                      aBase + mi * (16 * GSTR * 4) + s * 32);
            unsigned bv[4][2];
            ldsm4(bv[0][0], bv[0][1], bv[1][0], bv[1][1], bBase + s * 32);
            ldsm4(bv[2][0], bv[2][1], bv[3][0], bv[3][1],
                  bBase + 16 * GSTR * 4 + s * 32);
#pragma unroll
            for (int mi = 0; mi < 4; mi++)
#pragma unroll
                for (int nj = 0; nj < 4; nj++)
                    mma_f16(acc[mi][nj], av[mi], bv[nj][0], bv[nj][1]);
        }
        // no trailing sync: SYNC(kt+1) certifies compute(kt) completion
        stage++; if (stage >= NSTAGE) stage -= NSTAGE;
    }

    // epilogue
#pragma unroll
    for (int mi = 0; mi < 4; mi++) {
        const int r = m0 + wm * 64 + 16 * mi + gid;
#pragma unroll
        for (int nj = 0; nj < 4; nj++) {
            const int c = n0 + wn * 32 + 8 * nj + 2 * tig;
            if (MODE == 0) {
                float* C = (float*)C0;
                *(float2*)(C + (size_t)r * N + c) =
                    make_float2(acc[mi][nj][0], acc[mi][nj][1]);
                *(float2*)(C + (size_t)(r + 8) * N + c) =
                    make_float2(acc[mi][nj][2], acc[mi][nj][3]);
            } else {
                if (n0 < 2 * D_MODEL) {   // Q|K -> fp16, stride 2048
                    __half2* C = (__half2*)C0;
                    C[((size_t)r * 2048 + c) >> 1] =
                        __floats2half2_rn(acc[mi][nj][0], acc[mi][nj][1]);
                    C[((size_t)(r + 8) * 2048 + c) >> 1] =
                        __floats2half2_rn(acc[mi][nj][2], acc[mi][nj][3]);
                } else {                  // V -> transposed fp16: vt[(b*1024+d)][s]
                    __half* VT = (__half*)C1;
                    const int dg = c - 2 * D_MODEL;
                    const size_t base =
                        ((size_t)(r >> 11) * D_MODEL + dg) * SEQ + (r & 2047);
                    VT[base]            = __float2half_rn(acc[mi][nj][0]);
                    VT[base + SEQ]      = __float2half_rn(acc[mi][nj][1]);
                    VT[base + 8]        = __float2half_rn(acc[mi][nj][2]);
                    VT[base + SEQ + 8]  = __float2half_rn(acc[mi][nj][3]);
                }
            }
        }
    }
}

// ---------------------------------------------------------------------------
// Causal flash attention, all-fp16 mma, register-resident P, ldmatrix frags.
// 128-query tiles, 256 threads (8 warps x 16 rows), double-buffered K/V^T
// with ONE __syncthreads per key tile (issue moved after the barrier).
// Softmax in base-2 (log2e folded into the Q scale).
// ---------------------------------------------------------------------------
#define AKS 36
#define AKS_ELEMS (64 * AKS)
#define AVS 36
#define AVS_ELEMS (64 * AVS)
#define AQS 36
#define QROWS 128
#define SMEM_ATTN ((2 * AKS_ELEMS + 2 * AVS_ELEMS + QROWS * AQS) * 4)   // 55296 B

__global__ __launch_bounds__(256)
void attn_h(const __half* __restrict__ qk, const __half* __restrict__ vt,
            __half* __restrict__ out) {
    extern __shared__ unsigned sma[];
    unsigned* KsB = sma;                                 // [2][64][AKS]
    unsigned* VsB = sma + 2 * AKS_ELEMS;                 // [2][64 d][AVS]
    unsigned* Qs  = sma + 2 * AKS_ELEMS + 2 * AVS_ELEMS; // [128][AQS]
    const unsigned smb = (unsigned)__cvta_generic_to_shared(sma);

    const int qt   = gridDim.x - 1 - blockIdx.x;      // heavy tiles first
    const int h    = blockIdx.y;
    const int b    = blockIdx.z;
    const int t    = threadIdx.x;
    const int lane = t & 31;
    const int w    = t >> 5;        // 0..7
    const int gid  = lane >> 2;
    const int tig  = lane & 3;
    const int q0   = qt * QROWS;

    const int li  = lane & 7;
    const int q8  = (lane >> 3) & 1;
    const int q16 = lane >> 4;
    const unsigned kLane = ((unsigned)((q16 * 8 + li) * AKS + q8 * 4)) * 4;
    const unsigned vLane = ((unsigned)((q16 * 8 + li) * AVS + q8 * 4)) * 4;

    const __half* kbase  = qk + (size_t)(b * SEQ) * 2048 + D_MODEL + h * HD;
    const __half* vtbase = vt + ((size_t)b * D_MODEL + h * HD) * SEQ;

    auto load_kv = [&](int nb, int jt) {
        const __half* kp = kbase + (size_t)jt * 64 * 2048;
        const __half* vp = vtbase + jt * 64;
#pragma unroll
        for (int i = 0; i < 2; i++) {       // K: 64 rows x 8 chunks = 512
            const int c = t + i * 256;
            const int row = c >> 3, cc = c & 7;
            cp_async16(&KsB[nb * AKS_ELEMS + row * AKS + cc * 4],
                       kp + (size_t)row * 2048 + cc * 8);
        }
#pragma unroll
        for (int i = 0; i < 2; i++) {       // V^T: 64 d-rows x 8 chunks = 512
            const int c = t + i * 256;
            const int row = c >> 3, cc = c & 7;
            cp_async16(&VsB[nb * AVS_ELEMS + row * AVS + cc * 4],
                       vp + (size_t)row * SEQ + cc * 8);
        }
    };

    // prologue: Q tile (128 rows) + K/V tile 0
    {
        const __half* qp = qk + (size_t)(b * SEQ + q0) * 2048 + h * HD;
#pragma unroll
        for (int i = 0; i < 4; i++) {       // Q: 128 rows x 8 chunks = 1024
            const int c = t + i * 256;
            const int row = c >> 3, cc = c & 7;
            cp_async16(&Qs[row * AQS + cc * 4], qp + (size_t)row * 2048 + cc * 8);
        }
        load_kv(0, 0);
    }
    CP_COMMIT();
    CP_WAIT0();
    __syncthreads();

    // Q fragments -> registers, scaled by 0.125*log2(e) (base-2 softmax)
    unsigned qf[4][4];
    {
        const __half2 sc = __float2half2_rn(0.125f * 1.44269504f);
        const int r0 = (16 * w + gid) * AQS;
        const int r1 = (16 * w + gid + 8) * AQS;
#pragma unroll
        for (int s = 0; s < 4; s++) {
            unsigned u0 = Qs[r0 + 8 * s + tig];
            unsigned u1 = Qs[r1 + 8 * s + tig];
            unsigned u2 = Qs[r0 + 8 * s + tig + 4];
            unsigned u3 = Qs[r1 + 8 * s + tig + 4];
            __half2 h0 = __hmul2(*(__half2*)&u0, sc);
            __half2 h1 = __hmul2(*(__half2*)&u1, sc);
            __half2 h2 = __hmul2(*(__half2*)&u2, sc);
            __half2 h3 = __hmul2(*(__half2*)&u3, sc);
            qf[s][0] = *(unsigned*)&h0;
            qf[s][1] = *(unsigned*)&h1;
            qf[s][2] = *(unsigned*)&h2;
            qf[s][3] = *(unsigned*)&h3;
        }
    }

    float o[8][4];
#pragma unroll
    for (int j = 0; j < 8; j++)
#pragma unroll
        for (int e = 0; e < 4; e++) o[j][e] = 0.f;
    float m0 = -1e30f, m1 = -1e30f, l0 = 0.f, l1 = 0.f;

    const int row0 = q0 + 16 * w + gid;
    const int jt_max = 2 * qt + 1;

    for (int jt = 0; jt <= jt_max; jt++) {
        const int cur = jt & 1;
        CP_WAIT0();        // tile jt's group (issued last iteration / prologue)
        __syncthreads();   // data visible; all warps done reading buf cur^1

        if (jt + 1 <= jt_max) {
            load_kv(cur ^ 1, jt + 1);
            CP_COMMIT();
        }

        const unsigned kBase = smb + (unsigned)(cur * AKS_ELEMS) * 4 + kLane;
        const unsigned vBase = smb + (unsigned)((2 * AKS_ELEMS) + cur * AVS_ELEMS) * 4 + vLane;
        const int k0 = jt * 64;

        // S = Q K^T (fp16, 4 k16-steps, K frags via ldmatrix x4 per j-pair)
        float sacc[8][4];
#pragma unroll
        for (int j = 0; j < 8; j++)
#pragma unroll
            for (int e = 0; e < 4; e++) sacc[j][e] = 0.f;

#pragma unroll
        for (int s = 0; s < 4; s++) {
#pragma unroll
            for (int p = 0; p < 4; p++) {
                unsigned k0r, k1r, k2r, k3r;
                ldsm4(k0r, k1r, k2r, k3r, kBase + p * (16 * AKS * 4) + s * 32);
                mma_f16(sacc[2 * p],     qf[s], k0r, k1r);
                mma_f16(sacc[2 * p + 1], qf[s], k2r, k3r);
            }
        }

        // mask (only last two tiles cross the diagonal) + row max
        const bool need_mask = (jt >= 2 * qt);
        float mt0 = -1e30f, mt1 = -1e30f;
#pragma unroll
        for (int j = 0; j < 8; j++) {
            const int cb = k0 + 8 * j + 2 * tig;
            if (need_mask) {
                if (cb     > row0)     sacc[j][0] = -1e30f;
                if (cb + 1 > row0)     sacc[j][1] = -1e30f;
                if (cb     > row0 + 8) sacc[j][2] = -1e30f;
                if (cb + 1 > row0 + 8) sacc[j][3] = -1e30f;
            }
            mt0 = fmaxf(mt0, fmaxf(sacc[j][0], sacc[j][1]));
            mt1 = fmaxf(mt1, fmaxf(sacc[j][2], sacc[j][3]));
        }
        mt0 = fmaxf(mt0, __shfl_xor_sync(0xffffffffu, mt0, 1));
        mt0 = fmaxf(mt0, __shfl_xor_sync(0xffffffffu, mt0, 2));
        mt1 = fmaxf(mt1, __shfl_xor_sync(0xffffffffu, mt1, 1));
        mt1 = fmaxf(mt1, __shfl_xor_sync(0xffffffffu, mt1, 2));

        const float mn0 = fmaxf(m0, mt0);
        const float mn1 = fmaxf(m1, mt1);
        const float al0 = fexp2(m0 - mn0);
        const float al1 = fexp2(m1 - mn1);
        m0 = mn0; m1 = mn1;

        // P = 2^(S - m): pack fp16 A-fragments in registers
        unsigned pf[4][4];
        float ls0 = 0.f, ls1 = 0.f;
#pragma unroll
        for (int j = 0; j < 8; j++) {
            float p00 = fexp2(sacc[j][0] - mn0);
            float p01 = fexp2(sacc[j][1] - mn0);
            float p10 = fexp2(sacc[j][2] - mn1);
            float p11 = fexp2(sacc[j][3] - mn1);
            ls0 += p00 + p01;
            ls1 += p10 + p11;
            __half2 lo = __floats2half2_rn(p00, p01);
            __half2 hi = __floats2half2_rn(p10, p11);
            const int m = j >> 1;
            const int off = (j & 1) << 1;
            pf[m][off]     = *(unsigned*)&lo;
            pf[m][off + 1] = *(unsigned*)&hi;
        }
        ls0 += __shfl_xor_sync(0xffffffffu, ls0, 1);
        ls0 += __shfl_xor_sync(0xffffffffu, ls0, 2);
        ls1 += __shfl_xor_sync(0xffffffffu, ls1, 1);
        ls1 += __shfl_xor_sync(0xffffffffu, ls1, 2);
        l0 = l0 * al0 + ls0;
        l1 = l1 * al1 + ls1;

#pragma unroll
        for (int j = 0; j < 8; j++) {
            o[j][0] *= al0; o[j][1] *= al0;
            o[j][2] *= al1; o[j][3] *= al1;
        }

        // O += P V (fp16, V^T frags via ldmatrix x4 per j-pair)
#pragma unroll
        for (int m = 0; m < 4; m++) {
#pragma unroll
            for (int p = 0; p < 4; p++) {
                unsigned v0, v1, v2, v3;
                ldsm4(v0, v1, v2, v3, vBase + p * (16 * AVS * 4) + m * 32);
                mma_f16(o[2 * p],     pf[m], v0, v1);
                mma_f16(o[2 * p + 1], pf[m], v2, v3);
            }
        }
        // no trailing sync: next iteration's SYNC certifies completion
    }

    // epilogue -> fp16 for the output projection
    const float i0 = 1.f / l0;
    const float i1 = 1.f / l1;
    __half2* op0 = (__half2*)(out + (size_t)(b * SEQ + row0) * D_MODEL + h * HD);
    __half2* op1 = (__half2*)(out + (size_t)(b * SEQ + row0 + 8) * D_MODEL + h * HD);
#pragma unroll
    for (int j = 0; j < 8; j++) {
        const int c = (8 * j + 2 * tig) >> 1;
        op0[c] = __floats2half2_rn(o[j][0] * i0, o[j][1] * i0);
        op1[c] = __floats2half2_rn(o[j][2] * i1, o[j][3] * i1);
    }
}

extern "C" void kernel_launch(void* const* d_in, const int* in_sizes, int n_in,
                              void* d_out, int out_size) {
    const float* x     = (const float*)d_in[0];
    const float* w_qkv = (const float*)d_in[1];
    const float* w_o   = (const float*)d_in[2];
    float* out         = (float*)d_out;

    __half *qkh, *vt, *ao, *xh, *wqh, *woh;
    cudaGetSymbolAddress((void**)&qkh, g_qkh);
    cudaGetSymbolAddress((void**)&vt,  g_vt);
    cudaGetSymbolAddress((void**)&ao,  g_ao);
    cudaGetSymbolAddress((void**)&xh,  g_xh);
    cudaGetSymbolAddress((void**)&wqh, g_wqh);
    cudaGetSymbolAddress((void**)&woh, g_woh);

    static bool attr_set = false;
    if (!attr_set) {
        cudaFuncSetAttribute(gemm_h<0>, cudaFuncAttributeMaxDynamicSharedMemorySize, SMEM_GEMM);
        cudaFuncSetAttribute(gemm_h<1>, cudaFuncAttributeMaxDynamicSharedMemorySize, SMEM_GEMM);
        cudaFuncSetAttribute(attn_h, cudaFuncAttributeMaxDynamicSharedMemorySize, SMEM_ATTN);
        attr_set = true;
    }

    // 0) fp32 -> fp16 pre-pass
    conv_h<<<CONV_BLOCKS, 256>>>((const float4*)x, (const float4*)w_qkv, (const float4*)w_o,
                                 (uint2*)xh, (uint2*)wqh, (uint2*)woh);

    // 1) QKV projection (fp16 mma): Q|K -> fp16, V -> transposed fp16
    gemm_h<1><<<dim3(QKV_W / 128, M_TOT / 128), 256, SMEM_GEMM>>>(
        xh, wqh, qkh, vt, M_TOT, QKV_W, D_MODEL);

    // 2) causal attention -> fp16
    attn_h<<<dim3(SEQ / QROWS, NHEAD, BATCH), 256, SMEM_ATTN>>>(qkh, vt, ao);

    // 3) output projection (fp16 mma) -> fp32
    gemm_h<0><<<dim3(D_MODEL / 128, M_TOT / 128), 256, SMEM_GEMM>>>(
        ao, woh, out, nullptr, M_TOT, D_MODEL, D_MODEL);
}

// round 13
// speedup vs baseline: 2.1304x; 1.0122x over previous
#include <cuda_runtime.h>
#include <cuda_fp16.h>
#include <cstdint>

#define D_MODEL 1024
#define NHEAD   16
#define HD      64
#define SEQ     2048
#define BATCH   2
#define M_TOT   (BATCH * SEQ)   // 4096
#define QKV_W   (3 * D_MODEL)   // 3072

// Scratch (no cudaMalloc allowed).
__device__ __half g_qkh[(size_t)M_TOT * 2 * D_MODEL];  // Q|K fp16 [4096][2048]
__device__ __half g_vt [(size_t)M_TOT * D_MODEL];      // V^T fp16 [(b*1024+d)][2048 s]
__device__ __half g_ao [(size_t)M_TOT * D_MODEL];      // attn out fp16
__device__ __half g_xh [(size_t)M_TOT * D_MODEL];      // x -> fp16
__device__ __half g_wqh[(size_t)QKV_W * D_MODEL];      // w_qkv -> fp16
__device__ __half g_woh[(size_t)D_MODEL * D_MODEL];    // w_o -> fp16

// fp16 mma: D(fp32) += A(f16 m16k16 row) x B(f16 k16n8 col)
__device__ __forceinline__ void mma_f16(float* c, const unsigned* a,
                                        unsigned b0, unsigned b1) {
    asm volatile(
        "mma.sync.aligned.m16n8k16.row.col.f32.f16.f16.f32 "
        "{%0,%1,%2,%3},{%4,%5,%6,%7},{%8,%9},{%0,%1,%2,%3};\n"
        : "+f"(c[0]), "+f"(c[1]), "+f"(c[2]), "+f"(c[3])
        : "r"(a[0]), "r"(a[1]), "r"(a[2]), "r"(a[3]), "r"(b0), "r"(b1));
}

__device__ __forceinline__ void ldsm4(unsigned& r0, unsigned& r1,
                                      unsigned& r2, unsigned& r3, unsigned addr) {
    asm volatile("ldmatrix.sync.aligned.m8n8.x4.shared.b16 {%0,%1,%2,%3}, [%4];"
                 : "=r"(r0), "=r"(r1), "=r"(r2), "=r"(r3) : "r"(addr));
}

__device__ __forceinline__ float fexp2(float x) {
    float r;
    asm("ex2.approx.ftz.f32 %0, %1;" : "=f"(r) : "f"(x));
    return r;
}

__device__ __forceinline__ void cp_async16(void* smem_dst, const void* gmem_src) {
    unsigned s = (unsigned)__cvta_generic_to_shared(smem_dst);
    asm volatile("cp.async.cg.shared.global [%0], [%1], 16;\n" :: "r"(s), "l"(gmem_src));
}
#define CP_COMMIT() asm volatile("cp.async.commit_group;\n" ::: "memory")
#define CP_WAIT1()  asm volatile("cp.async.wait_group 1;\n" ::: "memory")
#define CP_WAIT0()  asm volatile("cp.async.wait_group 0;\n" ::: "memory")

// ---------------------------------------------------------------------------
// fp32 -> fp16 pre-pass (x, w_qkv, w_o)
// ---------------------------------------------------------------------------
#define XC_F4 ((M_TOT * D_MODEL) / 4)
#define WQ_F4 ((QKV_W * D_MODEL) / 4)
#define WO_F4 ((D_MODEL * D_MODEL) / 4)
#define CONV_BLOCKS ((XC_F4 + WQ_F4 + WO_F4) / 256)

__global__ void conv_h(const float4* __restrict__ x,
                       const float4* __restrict__ wq,
                       const float4* __restrict__ wo,
                       uint2* __restrict__ ox,
                       uint2* __restrict__ owq,
                       uint2* __restrict__ owo) {
    const int idx = blockIdx.x * 256 + threadIdx.x;
    const float4* src;
    uint2* dst;
    int i;
    if (idx < XC_F4)                { src = x;  dst = ox;  i = idx; }
    else if (idx < XC_F4 + WQ_F4)   { src = wq; dst = owq; i = idx - XC_F4; }
    else                            { src = wo; dst = owo; i = idx - XC_F4 - WQ_F4; }
    float4 v = src[i];
    __half2 lo = __floats2half2_rn(v.x, v.y);
    __half2 hi = __floats2half2_rn(v.z, v.w);
    dst[i] = make_uint2(*(unsigned*)&lo, *(unsigned*)&hi);
}

// ---------------------------------------------------------------------------
// fp16 GEMM with ldmatrix fragment loads.
// 128x128 block tile, K-tile 64 halves, 256 threads (8 warps, 64x32 tiles),
// 3-stage cp.async pipeline, ONE __syncthreads per K-tile, 2 CTAs/SM.
// s=0 fragments loaded before issuing next tile's cp.asyncs.
// MODE 0: fp32 out -> C0.
// MODE 1: cols<2048 -> fp16 C0 (Q|K, stride 2048); cols>=2048 -> V^T fp16 C1.
// ---------------------------------------------------------------------------
#define NSTAGE 3
#define GSTR 36                 // u32 per smem row (32 data + 4 pad)
#define GTILE (128 * GSTR)
#define SMEM_GEMM (2 * NSTAGE * GTILE * 4)   // 110592 B

template <int MODE>
__global__ __launch_bounds__(256, 2)
void gemm_h(const __half* __restrict__ A, const __half* __restrict__ B,
            void* __restrict__ C0, void* __restrict__ C1, int M, int N, int K) {
    extern __shared__ unsigned smg[];
    unsigned* Abuf = smg;
    unsigned* Bbuf = smg + NSTAGE * GTILE;
    const unsigned smb = (unsigned)__cvta_generic_to_shared(smg);

    const int t    = threadIdx.x;
    const int lane = t & 31;
    const int w    = t >> 5;
    const int gid  = lane >> 2;
    const int tig  = lane & 3;
    const int wm   = w & 1;
    const int wn   = w >> 1;
    const int m0   = blockIdx.y * 128;
    const int n0   = blockIdx.x * 128;

    const int li  = lane & 7;
    const int q8  = (lane >> 3) & 1;
    const int q16 = lane >> 4;
    const unsigned aLane = ((unsigned)((wm * 64 + q8 * 8 + li) * GSTR + q16 * 4)) * 4;
    const unsigned bLane = ((unsigned)((wn * 32 + q16 * 8 + li) * GSTR + q8 * 4)) * 4;

    float acc[4][4][4];
#pragma unroll
    for (int i = 0; i < 4; i++)
#pragma unroll
        for (int j = 0; j < 4; j++)
#pragma unroll
            for (int e = 0; e < 4; e++) acc[i][j][e] = 0.f;

    const int nkt = K / 64;

    auto issue = [&](int stage, int kt) {
        unsigned* as = Abuf + stage * GTILE;
        unsigned* bs = Bbuf + stage * GTILE;
        const __half* Ag = A + (size_t)m0 * K + kt * 64;
        const __half* Bg = B + (size_t)n0 * K + kt * 64;
#pragma unroll
        for (int i = 0; i < 4; i++) {
            const int c = t + i * 256;           // 0..1023
            const int row = c >> 3, cc = c & 7;
            cp_async16(&as[row * GSTR + cc * 4], Ag + (size_t)row * K + cc * 8);
            cp_async16(&bs[row * GSTR + cc * 4], Bg + (size_t)row * K + cc * 8);
        }
    };

    issue(0, 0); CP_COMMIT();
    issue(1, 1); CP_COMMIT();

    int stage = 0;
    for (int kt = 0; kt < nkt; kt++) {
        if (kt + 1 < nkt) { CP_WAIT1(); } else { CP_WAIT0(); }
        __syncthreads();   // tile kt visible; all warps done with buf (kt-1)%3

        const unsigned aBase = smb + (unsigned)(stage * GTILE) * 4 + aLane;
        const unsigned bBase = smb + (unsigned)((NSTAGE + stage) * GTILE) * 4 + bLane;

        // s=0 fragments first: start the LDSM->HMMA chain before LSU work
        unsigned av[4][4], bv[4][2];
#pragma unroll
        for (int mi = 0; mi < 4; mi++)
            ldsm4(av[mi][0], av[mi][1], av[mi][2], av[mi][3],
                  aBase + mi * (16 * GSTR * 4));
        ldsm4(bv[0][0], bv[0][1], bv[1][0], bv[1][1], bBase);
        ldsm4(bv[2][0], bv[2][1], bv[3][0], bv[3][1], bBase + 16 * GSTR * 4);

        if (kt + 2 < nkt) {
            int ns = stage + 2; if (ns >= NSTAGE) ns -= NSTAGE;
            issue(ns, kt + 2);
            CP_COMMIT();
        }

#pragma unroll
        for (int mi = 0; mi < 4; mi++)
#pragma unroll
            for (int nj = 0; nj < 4; nj++)
                mma_f16(acc[mi][nj], av[mi], bv[nj][0], bv[nj][1]);

#pragma unroll
        for (int s = 1; s < 4; s++) {
#pragma unroll
            for (int mi = 0; mi < 4; mi++)
                ldsm4(av[mi][0], av[mi][1], av[mi][2], av[mi][3],
                      aBase + mi * (16 * GSTR * 4) + s * 32);
            ldsm4(bv[0][0], bv[0][1], bv[1][0], bv[1][1], bBase + s * 32);
            ldsm4(bv[2][0], bv[2][1], bv[3][0], bv[3][1],
                  bBase + 16 * GSTR * 4 + s * 32);
#pragma unroll
            for (int mi = 0; mi < 4; mi++)
#pragma unroll
                for (int nj = 0; nj < 4; nj++)
                    mma_f16(acc[mi][nj], av[mi], bv[nj][0], bv[nj][1]);
        }
        // no trailing sync: SYNC(kt+1) certifies compute(kt) completion
        stage++; if (stage >= NSTAGE) stage -= NSTAGE;
    }

    // epilogue
#pragma unroll
    for (int mi = 0; mi < 4; mi++) {
        const int r = m0 + wm * 64 + 16 * mi + gid;
#pragma unroll
        for (int nj = 0; nj < 4; nj++) {
            const int c = n0 + wn * 32 + 8 * nj + 2 * tig;
            if (MODE == 0) {
                float* C = (float*)C0;
                *(float2*)(C + (size_t)r * N + c) =
                    make_float2(acc[mi][nj][0], acc[mi][nj][1]);
                *(float2*)(C + (size_t)(r + 8) * N + c) =
                    make_float2(acc[mi][nj][2], acc[mi][nj][3]);
            } else {
                if (n0 < 2 * D_MODEL) {   // Q|K -> fp16, stride 2048
                    __half2* C = (__half2*)C0;
                    C[((size_t)r * 2048 + c) >> 1] =
                        __floats2half2_rn(acc[mi][nj][0], acc[mi][nj][1]);
                    C[((size_t)(r + 8) * 2048 + c) >> 1] =
                        __floats2half2_rn(acc[mi][nj][2], acc[mi][nj][3]);
                } else {                  // V -> transposed fp16: vt[(b*1024+d)][s]
                    __half* VT = (__half*)C1;
                    const int dg = c - 2 * D_MODEL;
                    const size_t base =
                        ((size_t)(r >> 11) * D_MODEL + dg) * SEQ + (r & 2047);
                    VT[base]            = __float2half_rn(acc[mi][nj][0]);
                    VT[base + SEQ]      = __float2half_rn(acc[mi][nj][1]);
                    VT[base + 8]        = __float2half_rn(acc[mi][nj][2]);
                    VT[base + SEQ + 8]  = __float2half_rn(acc[mi][nj][3]);
                }
            }
        }
    }
}

// ---------------------------------------------------------------------------
// Causal flash attention, all-fp16 mma, register-resident P, ldmatrix frags.
// 128-query tiles, 256 threads (8 warps x 16 rows).
// Key tiles processed in PAIRS: 4 K/V buffers, ONE wait+sync per 2 tiles.
// Per-warp causal skip: tiles fully above the diagonal are skipped (bit-exact).
// Softmax in base-2 (log2e folded into the Q scale).
// ---------------------------------------------------------------------------
#define AKS 36
#define AKS_ELEMS (64 * AKS)
#define AVS 36
#define AVS_ELEMS (64 * AVS)
#define AQS 36
#define QROWS 128
#define SMEM_ATTN ((4 * AKS_ELEMS + 4 * AVS_ELEMS + QROWS * AQS) * 4)   // 92160 B

__global__ __launch_bounds__(256)
void attn_h(const __half* __restrict__ qk, const __half* __restrict__ vt,
            __half* __restrict__ out) {
    extern __shared__ unsigned sma[];
    unsigned* KsB = sma;                                 // [4][64][AKS]
    unsigned* VsB = sma + 4 * AKS_ELEMS;                 // [4][64 d][AVS]
    unsigned* Qs  = sma + 4 * AKS_ELEMS + 4 * AVS_ELEMS; // [128][AQS]
    const unsigned smb = (unsigned)__cvta_generic_to_shared(sma);

    const int qt   = gridDim.x - 1 - blockIdx.x;      // heavy tiles first
    const int h    = blockIdx.y;
    const int b    = blockIdx.z;
    const int t    = threadIdx.x;
    const int lane = t & 31;
    const int w    = t >> 5;        // 0..7
    const int gid  = lane >> 2;
    const int tig  = lane & 3;
    const int q0   = qt * QROWS;

    const int li  = lane & 7;
    const int q8  = (lane >> 3) & 1;
    const int q16 = lane >> 4;
    const unsigned kLane = ((unsigned)((q16 * 8 + li) * AKS + q8 * 4)) * 4;
    const unsigned vLane = ((unsigned)((q16 * 8 + li) * AVS + q8 * 4)) * 4;

    const __half* kbase  = qk + (size_t)(b * SEQ) * 2048 + D_MODEL + h * HD;
    const __half* vtbase = vt + ((size_t)b * D_MODEL + h * HD) * SEQ;

    auto load_kv = [&](int nb, int jt) {
        const __half* kp = kbase + (size_t)jt * 64 * 2048;
        const __half* vp = vtbase + jt * 64;
#pragma unroll
        for (int i = 0; i < 2; i++) {       // K: 64 rows x 8 chunks = 512
            const int c = t + i * 256;
            const int row = c >> 3, cc = c & 7;
            cp_async16(&KsB[nb * AKS_ELEMS + row * AKS + cc * 4],
                       kp + (size_t)row * 2048 + cc * 8);
        }
#pragma unroll
        for (int i = 0; i < 2; i++) {       // V^T: 64 d-rows x 8 chunks = 512
            const int c = t + i * 256;
            const int row = c >> 3, cc = c & 7;
            cp_async16(&VsB[nb * AVS_ELEMS + row * AVS + cc * 4],
                       vp + (size_t)row * SEQ + cc * 8);
        }
    };

    // prologue: Q tile (128 rows) + key-tile pair 0 (tiles 0,1 -> bufs 0,1)
    {
        const __half* qp = qk + (size_t)(b * SEQ + q0) * 2048 + h * HD;
#pragma unroll
        for (int i = 0; i < 4; i++) {       // Q: 128 rows x 8 chunks = 1024
            const int c = t + i * 256;
            const int row = c >> 3, cc = c & 7;
            cp_async16(&Qs[row * AQS + cc * 4], qp + (size_t)row * 2048 + cc * 8);
        }
        load_kv(0, 0);
        load_kv(1, 1);
    }
    CP_COMMIT();
    CP_WAIT0();
    __syncthreads();

    // Q fragments -> registers, scaled by 0.125*log2(e) (base-2 softmax)
    unsigned qf[4][4];
    {
        const __half2 sc = __float2half2_rn(0.125f * 1.44269504f);
        const int r0 = (16 * w + gid) * AQS;
        const int r1 = (16 * w + gid + 8) * AQS;
#pragma unroll
        for (int s = 0; s < 4; s++) {
            unsigned u0 = Qs[r0 + 8 * s + tig];
            unsigned u1 = Qs[r1 + 8 * s + tig];
            unsigned u2 = Qs[r0 + 8 * s + tig + 4];
            unsigned u3 = Qs[r1 + 8 * s + tig + 4];
            __half2 h0 = __hmul2(*(__half2*)&u0, sc);
            __half2 h1 = __hmul2(*(__half2*)&u1, sc);
            __half2 h2 = __hmul2(*(__half2*)&u2, sc);
            __half2 h3 = __hmul2(*(__half2*)&u3, sc);
            qf[s][0] = *(unsigned*)&h0;
            qf[s][1] = *(unsigned*)&h1;
            qf[s][2] = *(unsigned*)&h2;
            qf[s][3] = *(unsigned*)&h3;
        }
    }

    float o[8][4];
#pragma unroll
    for (int j = 0; j < 8; j++)
#pragma unroll
        for (int e = 0; e < 4; e++) o[j][e] = 0.f;
    float m0 = -1e30f, m1 = -1e30f, l0 = 0.f, l1 = 0.f;

    const int row0    = q0 + 16 * w + gid;
    const int rowWmin = q0 + 16 * w;          // warp's lowest query row
    const int rowWmax = rowWmin + 15;         // warp's highest query row
    const int npair   = qt + 1;               // key tiles = 2*(qt+1), paired

    for (int p = 0; p < npair; p++) {
        CP_WAIT0();        // pair p's loads complete
        __syncthreads();   // visible; all warps done with the other buffer half

        if (p + 1 < npair) {
            const int nb = 2 * ((p + 1) & 1);
            load_kv(nb,     2 * p + 2);
            load_kv(nb + 1, 2 * p + 3);
            CP_COMMIT();
        }

#pragma unroll
        for (int half = 0; half < 2; half++) {
            const int jt = 2 * p + half;
            const int k0 = jt * 64;
            if (k0 > rowWmax) continue;       // tile fully above diagonal: exact no-op

            const int buf = 2 * (p & 1) + half;
            const unsigned kBase = smb + (unsigned)(buf * AKS_ELEMS) * 4 + kLane;
            const unsigned vBase = smb + (unsigned)(4 * AKS_ELEMS + buf * AVS_ELEMS) * 4 + vLane;

            // S = Q K^T (fp16, 4 k16-steps)
            float sacc[8][4];
#pragma unroll
            for (int j = 0; j < 8; j++)
#pragma unroll
                for (int e = 0; e < 4; e++) sacc[j][e] = 0.f;

#pragma unroll
            for (int s = 0; s < 4; s++) {
#pragma unroll
                for (int pp = 0; pp < 4; pp++) {
                    unsigned k0r, k1r, k2r, k3r;
                    ldsm4(k0r, k1r, k2r, k3r, kBase + pp * (16 * AKS * 4) + s * 32);
                    mma_f16(sacc[2 * pp],     qf[s], k0r, k1r);
                    mma_f16(sacc[2 * pp + 1], qf[s], k2r, k3r);
                }
            }

            // mask (per-warp: only tiles crossing this warp's rows) + row max
            const bool need_mask = (k0 + 63 > rowWmin);
            float mt0 = -1e30f, mt1 = -1e30f;
#pragma unroll
            for (int j = 0; j < 8; j++) {
                const int cb = k0 + 8 * j + 2 * tig;
                if (need_mask) {
                    if (cb     > row0)     sacc[j][0] = -1e30f;
                    if (cb + 1 > row0)     sacc[j][1] = -1e30f;
                    if (cb     > row0 + 8) sacc[j][2] = -1e30f;
                    if (cb + 1 > row0 + 8) sacc[j][3] = -1e30f;
                }
                mt0 = fmaxf(mt0, fmaxf(sacc[j][0], sacc[j][1]));
                mt1 = fmaxf(mt1, fmaxf(sacc[j][2], sacc[j][3]));
            }
            mt0 = fmaxf(mt0, __shfl_xor_sync(0xffffffffu, mt0, 1));
            mt0 = fmaxf(mt0, __shfl_xor_sync(0xffffffffu, mt0, 2));
            mt1 = fmaxf(mt1, __shfl_xor_sync(0xffffffffu, mt1, 1));
            mt1 = fmaxf(mt1, __shfl_xor_sync(0xffffffffu, mt1, 2));

            const float mn0 = fmaxf(m0, mt0);
            const float mn1 = fmaxf(m1, mt1);
            const float al0 = fexp2(m0 - mn0);
            const float al1 = fexp2(m1 - mn1);
            m0 = mn0; m1 = mn1;

            // P = 2^(S - m): pack fp16 A-fragments in registers
            unsigned pf[4][4];
            float ls0 = 0.f, ls1 = 0.f;
#pragma unroll
            for (int j = 0; j < 8; j++) {
                float p00 = fexp2(sacc[j][0] - mn0);
                float p01 = fexp2(sacc[j][1] - mn0);
                float p10 = fexp2(sacc[j][2] - mn1);
                float p11 = fexp2(sacc[j][3] - mn1);
                ls0 += p00 + p01;
                ls1 += p10 + p11;
                __half2 lo = __floats2half2_rn(p00, p01);
                __half2 hi = __floats2half2_rn(p10, p11);
                const int mm = j >> 1;
                const int off = (j & 1) << 1;
                pf[mm][off]     = *(unsigned*)&lo;
                pf[mm][off + 1] = *(unsigned*)&hi;
            }
            ls0 += __shfl_xor_sync(0xffffffffu, ls0, 1);
            ls0 += __shfl_xor_sync(0xffffffffu, ls0, 2);
            ls1 += __shfl_xor_sync(0xffffffffu, ls1, 1);
            ls1 += __shfl_xor_sync(0xffffffffu, ls1, 2);
            l0 = l0 * al0 + ls0;
            l1 = l1 * al1 + ls1;

#pragma unroll
            for (int j = 0; j < 8; j++) {
                o[j][0] *= al0; o[j][1] *= al0;
                o[j][2] *= al1; o[j][3] *= al1;
            }

            // O += P V (fp16, V^T frags via ldmatrix x4 per j-pair)
#pragma unroll
            for (int mm = 0; mm < 4; mm++) {
#pragma unroll
                for (int pp = 0; pp < 4; pp++) {
                    unsigned v0, v1, v2, v3;
                    ldsm4(v0, v1, v2, v3, vBase + pp * (16 * AVS * 4) + mm * 32);
                    mma_f16(o[2 * pp],     pf[mm], v0, v1);
                    mma_f16(o[2 * pp + 1], pf[mm], v2, v3);
                }
            }
        }
        // no trailing sync: next pair's SYNC certifies completion
    }

    // epilogue -> fp16 for the output projection
    const float i0 = 1.f / l0;
    const float i1 = 1.f / l1;
    __half2* op0 = (__half2*)(out + (size_t)(b * SEQ + row0) * D_MODEL + h * HD);
    __half2* op1 = (__half2*)(out + (size_t)(b * SEQ + row0 + 8) * D_MODEL + h * HD);
#pragma unroll
    for (int j = 0; j < 8; j++) {
        const int c = (8 * j + 2 * tig) >> 1;
        op0[c] = __floats2half2_rn(o[j][0] * i0, o[j][1] * i0);
        op1[c] = __floats2half2_rn(o[j][2] * i1, o[j][3] * i1);
    }
}

extern "C" void kernel_launch(void* const* d_in, const int* in_sizes, int n_in,
                              void* d_out, int out_size) {
    const float* x     = (const float*)d_in[0];
    const float* w_qkv = (const float*)d_in[1];
    const float* w_o   = (const float*)d_in[2];
    float* out         = (float*)d_out;

    __half *qkh, *vt, *ao, *xh, *wqh, *woh;
    cudaGetSymbolAddress((void**)&qkh, g_qkh);
    cudaGetSymbolAddress((void**)&vt,  g_vt);
    cudaGetSymbolAddress((void**)&ao,  g_ao);
    cudaGetSymbolAddress((void**)&xh,  g_xh);
    cudaGetSymbolAddress((void**)&wqh, g_wqh);
    cudaGetSymbolAddress((void**)&woh, g_woh);

    static bool attr_set = false;
    if (!attr_set) {
        cudaFuncSetAttribute(gemm_h<0>, cudaFuncAttributeMaxDynamicSharedMemorySize, SMEM_GEMM);
        cudaFuncSetAttribute(gemm_h<1>, cudaFuncAttributeMaxDynamicSharedMemorySize, SMEM_GEMM);
        cudaFuncSetAttribute(attn_h, cudaFuncAttributeMaxDynamicSharedMemorySize, SMEM_ATTN);
        attr_set = true;
    }

    // 0) fp32 -> fp16 pre-pass
    conv_h<<<CONV_BLOCKS, 256>>>((const float4*)x, (const float4*)w_qkv, (const float4*)w_o,
                                 (uint2*)xh, (uint2*)wqh, (uint2*)woh);

    // 1) QKV projection (fp16 mma): Q|K -> fp16, V -> transposed fp16
    gemm_h<1><<<dim3(QKV_W / 128, M_TOT / 128), 256, SMEM_GEMM>>>(
        xh, wqh, qkh, vt, M_TOT, QKV_W, D_MODEL);

    // 2) causal attention -> fp16
    attn_h<<<dim3(SEQ / QROWS, NHEAD, BATCH), 256, SMEM_ATTN>>>(qkh, vt, ao);

    // 3) output projection (fp16 mma) -> fp32
    gemm_h<0><<<dim3(D_MODEL / 128, M_TOT / 128), 256, SMEM_GEMM>>>(
        ao, woh, out, nullptr, M_TOT, D_MODEL, D_MODEL);
}

// round 14
// speedup vs baseline: 2.3436x; 1.1001x over previous
#include <cuda_runtime.h>
#include <cuda_fp16.h>
#include <cstdint>

#define D_MODEL 1024
#define NHEAD   16
#define HD      64
#define SEQ     2048
#define BATCH   2
#define M_TOT   (BATCH * SEQ)   // 4096
#define QKV_W   (3 * D_MODEL)   // 3072

// Scratch (no cudaMalloc allowed).
__device__ __half g_qkh[(size_t)M_TOT * 2 * D_MODEL];  // Q|K fp16 [4096][2048]
__device__ __half g_vt [(size_t)M_TOT * D_MODEL];      // V^T fp16 [(b*1024+d)][2048 s]
__device__ __half g_ao [(size_t)M_TOT * D_MODEL];      // attn out fp16
__device__ __half g_xh [(size_t)M_TOT * D_MODEL];      // x -> fp16
__device__ __half g_wqh[(size_t)QKV_W * D_MODEL];      // w_qkv -> fp16
__device__ __half g_woh[(size_t)D_MODEL * D_MODEL];    // w_o -> fp16

// fp16 mma: D(fp32) += A(f16 m16k16 row) x B(f16 k16n8 col)
__device__ __forceinline__ void mma_f16(float* c, const unsigned* a,
                                        unsigned b0, unsigned b1) {
    asm volatile(
        "mma.sync.aligned.m16n8k16.row.col.f32.f16.f16.f32 "
        "{%0,%1,%2,%3},{%4,%5,%6,%7},{%8,%9},{%0,%1,%2,%3};\n"
        : "+f"(c[0]), "+f"(c[1]), "+f"(c[2]), "+f"(c[3])
        : "r"(a[0]), "r"(a[1]), "r"(a[2]), "r"(a[3]), "r"(b0), "r"(b1));
}

__device__ __forceinline__ void ldsm4(unsigned& r0, unsigned& r1,
                                      unsigned& r2, unsigned& r3, unsigned addr) {
    asm volatile("ldmatrix.sync.aligned.m8n8.x4.shared.b16 {%0,%1,%2,%3}, [%4];"
                 : "=r"(r0), "=r"(r1), "=r"(r2), "=r"(r3) : "r"(addr));
}

__device__ __forceinline__ float fexp2(float x) {
    float r;
    asm("ex2.approx.ftz.f32 %0, %1;" : "=f"(r) : "f"(x));
    return r;
}

__device__ __forceinline__ void cp_async16(void* smem_dst, const void* gmem_src) {
    unsigned s = (unsigned)__cvta_generic_to_shared(smem_dst);
    asm volatile("cp.async.cg.shared.global [%0], [%1], 16;\n" :: "r"(s), "l"(gmem_src));
}
#define CP_COMMIT() asm volatile("cp.async.commit_group;\n" ::: "memory")
#define CP_WAIT1()  asm volatile("cp.async.wait_group 1;\n" ::: "memory")
#define CP_WAIT0()  asm volatile("cp.async.wait_group 0;\n" ::: "memory")

// ---------------------------------------------------------------------------
// fp32 -> fp16 pre-pass (x, w_qkv, w_o)
// ---------------------------------------------------------------------------
#define XC_F4 ((M_TOT * D_MODEL) / 4)
#define WQ_F4 ((QKV_W * D_MODEL) / 4)
#define WO_F4 ((D_MODEL * D_MODEL) / 4)
#define CONV_BLOCKS ((XC_F4 + WQ_F4 + WO_F4) / 256)

__global__ void conv_h(const float4* __restrict__ x,
                       const float4* __restrict__ wq,
                       const float4* __restrict__ wo,
                       uint2* __restrict__ ox,
                       uint2* __restrict__ owq,
                       uint2* __restrict__ owo) {
    const int idx = blockIdx.x * 256 + threadIdx.x;
    const float4* src;
    uint2* dst;
    int i;
    if (idx < XC_F4)                { src = x;  dst = ox;  i = idx; }
    else if (idx < XC_F4 + WQ_F4)   { src = wq; dst = owq; i = idx - XC_F4; }
    else                            { src = wo; dst = owo; i = idx - XC_F4 - WQ_F4; }
    float4 v = src[i];
    __half2 lo = __floats2half2_rn(v.x, v.y);
    __half2 hi = __floats2half2_rn(v.z, v.w);
    dst[i] = make_uint2(*(unsigned*)&lo, *(unsigned*)&hi);
}

// ---------------------------------------------------------------------------
// fp16 GEMM with ldmatrix fragment loads.
// 128x128 block tile, K-tile 64 halves, 256 threads (8 warps, 64x32 tiles),
// 3-stage cp.async pipeline, ONE __syncthreads per K-tile, 2 CTAs/SM.
// MODE 0: fp32 out -> C0.
// MODE 1: cols<2048 -> fp16 C0 (Q|K, stride 2048); cols>=2048 -> V^T fp16 C1.
// ---------------------------------------------------------------------------
#define NSTAGE 3
#define GSTR 36                 // u32 per smem row (32 data + 4 pad)
#define GTILE (128 * GSTR)
#define SMEM_GEMM (2 * NSTAGE * GTILE * 4)   // 110592 B

template <int MODE>
__global__ __launch_bounds__(256, 2)
void gemm_h(const __half* __restrict__ A, const __half* __restrict__ B,
            void* __restrict__ C0, void* __restrict__ C1, int M, int N, int K) {
    extern __shared__ unsigned smg[];
    unsigned* Abuf = smg;
    unsigned* Bbuf = smg + NSTAGE * GTILE;
    const unsigned smb = (unsigned)__cvta_generic_to_shared(smg);

    const int t    = threadIdx.x;
    const int lane = t & 31;
    const int w    = t >> 5;
    const int gid  = lane >> 2;
    const int tig  = lane & 3;
    const int wm   = w & 1;
    const int wn   = w >> 1;
    const int m0   = blockIdx.y * 128;
    const int n0   = blockIdx.x * 128;

    const int li  = lane & 7;
    const int q8  = (lane >> 3) & 1;
    const int q16 = lane >> 4;
    const unsigned aLane = ((unsigned)((wm * 64 + q8 * 8 + li) * GSTR + q16 * 4)) * 4;
    const unsigned bLane = ((unsigned)((wn * 32 + q16 * 8 + li) * GSTR + q8 * 4)) * 4;

    float acc[4][4][4];
#pragma unroll
    for (int i = 0; i < 4; i++)
#pragma unroll
        for (int j = 0; j < 4; j++)
#pragma unroll
            for (int e = 0; e < 4; e++) acc[i][j][e] = 0.f;

    const int nkt = K / 64;

    auto issue = [&](int stage, int kt) {
        unsigned* as = Abuf + stage * GTILE;
        unsigned* bs = Bbuf + stage * GTILE;
        const __half* Ag = A + (size_t)m0 * K + kt * 64;
        const __half* Bg = B + (size_t)n0 * K + kt * 64;
#pragma unroll
        for (int i = 0; i < 4; i++) {
            const int c = t + i * 256;           // 0..1023
            const int row = c >> 3, cc = c & 7;
            cp_async16(&as[row * GSTR + cc * 4], Ag + (size_t)row * K + cc * 8);
            cp_async16(&bs[row * GSTR + cc * 4], Bg + (size_t)row * K + cc * 8);
        }
    };

    issue(0, 0); CP_COMMIT();
    issue(1, 1); CP_COMMIT();

    int stage = 0;
    for (int kt = 0; kt < nkt; kt++) {
        if (kt + 1 < nkt) { CP_WAIT1(); } else { CP_WAIT0(); }
        __syncthreads();   // tile kt visible; all warps done with buf (kt-1)%3

        const unsigned aBase = smb + (unsigned)(stage * GTILE) * 4 + aLane;
        const unsigned bBase = smb + (unsigned)((NSTAGE + stage) * GTILE) * 4 + bLane;

        // s=0 fragments first: start the LDSM->HMMA chain before LSU work
        unsigned av[4][4], bv[4][2];
#pragma unroll
        for (int mi = 0; mi < 4; mi++)
            ldsm4(av[mi][0], av[mi][1], av[mi][2], av[mi][3],
                  aBase + mi * (16 * GSTR * 4));
        ldsm4(bv[0][0], bv[0][1], bv[1][0], bv[1][1], bBase);
        ldsm4(bv[2][0], bv[2][1], bv[3][0], bv[3][1], bBase + 16 * GSTR * 4);

        if (kt + 2 < nkt) {
            int ns = stage + 2; if (ns >= NSTAGE) ns -= NSTAGE;
            issue(ns, kt + 2);
            CP_COMMIT();
        }

#pragma unroll
        for (int mi = 0; mi < 4; mi++)
#pragma unroll
            for (int nj = 0; nj < 4; nj++)
                mma_f16(acc[mi][nj], av[mi], bv[nj][0], bv[nj][1]);

#pragma unroll
        for (int s = 1; s < 4; s++) {
#pragma unroll
            for (int mi = 0; mi < 4; mi++)
                ldsm4(av[mi][0], av[mi][1], av[mi][2], av[mi][3],
                      aBase + mi * (16 * GSTR * 4) + s * 32);
            ldsm4(bv[0][0], bv[0][1], bv[1][0], bv[1][1], bBase + s * 32);
            ldsm4(bv[2][0], bv[2][1], bv[3][0], bv[3][1],
                  bBase + 16 * GSTR * 4 + s * 32);
#pragma unroll
            for (int mi = 0; mi < 4; mi++)
#pragma unroll
                for (int nj = 0; nj < 4; nj++)
                    mma_f16(acc[mi][nj], av[mi], bv[nj][0], bv[nj][1]);
        }
        stage++; if (stage >= NSTAGE) stage -= NSTAGE;
    }

    // epilogue
#pragma unroll
    for (int mi = 0; mi < 4; mi++) {
        const int r = m0 + wm * 64 + 16 * mi + gid;
#pragma unroll
        for (int nj = 0; nj < 4; nj++) {
            const int c = n0 + wn * 32 + 8 * nj + 2 * tig;
            if (MODE == 0) {
                float* C = (float*)C0;
                *(float2*)(C + (size_t)r * N + c) =
                    make_float2(acc[mi][nj][0], acc[mi][nj][1]);
                *(float2*)(C + (size_t)(r + 8) * N + c) =
                    make_float2(acc[mi][nj][2], acc[mi][nj][3]);
            } else {
                if (n0 < 2 * D_MODEL) {   // Q|K -> fp16, stride 2048
                    __half2* C = (__half2*)C0;
                    C[((size_t)r * 2048 + c) >> 1] =
                        __floats2half2_rn(acc[mi][nj][0], acc[mi][nj][1]);
                    C[((size_t)(r + 8) * 2048 + c) >> 1] =
                        __floats2half2_rn(acc[mi][nj][2], acc[mi][nj][3]);
                } else {                  // V -> transposed fp16: vt[(b*1024+d)][s]
                    __half* VT = (__half*)C1;
                    const int dg = c - 2 * D_MODEL;
                    const size_t base =
                        ((size_t)(r >> 11) * D_MODEL + dg) * SEQ + (r & 2047);
                    VT[base]            = __float2half_rn(acc[mi][nj][0]);
                    VT[base + SEQ]      = __float2half_rn(acc[mi][nj][1]);
                    VT[base + 8]        = __float2half_rn(acc[mi][nj][2]);
                    VT[base + SEQ + 8]  = __float2half_rn(acc[mi][nj][3]);
                }
            }
        }
    }
}

// ---------------------------------------------------------------------------
// Causal flash attention, all-fp16 mma, register-resident P, ldmatrix frags.
// 128-query tiles, 256 threads (8 warps x 16 rows), paired key tiles
// (4 buffers, one wait+sync per 2 tiles), per-warp causal skip, base-2 softmax.
// LOAD BALANCE: each block processes q-tiles (NQT-1-bx) and bx sequentially ->
// every block does exactly NQT+1 tile-pairs; 256 blocks = one uniform wave.
// ---------------------------------------------------------------------------
#define AKS 36
#define AKS_ELEMS (64 * AKS)
#define AVS 36
#define AVS_ELEMS (64 * AVS)
#define AQS 36
#define QROWS 128
#define NQT (SEQ / QROWS)     // 16
#define SMEM_ATTN ((4 * AKS_ELEMS + 4 * AVS_ELEMS + QROWS * AQS) * 4)   // 92160 B

__global__ __launch_bounds__(256)
void attn_h(const __half* __restrict__ qk, const __half* __restrict__ vt,
            __half* __restrict__ out) {
    extern __shared__ unsigned sma[];
    unsigned* KsB = sma;                                 // [4][64][AKS]
    unsigned* VsB = sma + 4 * AKS_ELEMS;                 // [4][64 d][AVS]
    unsigned* Qs  = sma + 4 * AKS_ELEMS + 4 * AVS_ELEMS; // [128][AQS]
    const unsigned smb = (unsigned)__cvta_generic_to_shared(sma);

    const int h    = blockIdx.y;
    const int b    = blockIdx.z;
    const int t    = threadIdx.x;
    const int lane = t & 31;
    const int w    = t >> 5;        // 0..7
    const int gid  = lane >> 2;
    const int tig  = lane & 3;

    const int li  = lane & 7;
    const int q8  = (lane >> 3) & 1;
    const int q16 = lane >> 4;
    const unsigned kLane = ((unsigned)((q16 * 8 + li) * AKS + q8 * 4)) * 4;
    const unsigned vLane = ((unsigned)((q16 * 8 + li) * AVS + q8 * 4)) * 4;

    const __half* kbase  = qk + (size_t)(b * SEQ) * 2048 + D_MODEL + h * HD;
    const __half* vtbase = vt + ((size_t)b * D_MODEL + h * HD) * SEQ;

    auto load_kv = [&](int nb, int jt) {
        const __half* kp = kbase + (size_t)jt * 64 * 2048;
        const __half* vp = vtbase + jt * 64;
#pragma unroll
        for (int i = 0; i < 2; i++) {       // K: 64 rows x 8 chunks = 512
            const int c = t + i * 256;
            const int row = c >> 3, cc = c & 7;
            cp_async16(&KsB[nb * AKS_ELEMS + row * AKS + cc * 4],
                       kp + (size_t)row * 2048 + cc * 8);
        }
#pragma unroll
        for (int i = 0; i < 2; i++) {       // V^T: 64 d-rows x 8 chunks = 512
            const int c = t + i * 256;
            const int row = c >> 3, cc = c & 7;
            cp_async16(&VsB[nb * AVS_ELEMS + row * AVS + cc * 4],
                       vp + (size_t)row * SEQ + cc * 8);
        }
    };

    for (int leg = 0; leg < 2; leg++) {
        const int qt = leg ? (int)blockIdx.x : (NQT - 1 - (int)blockIdx.x);
        const int q0 = qt * QROWS;

        __syncthreads();   // previous leg's buffer reads fully done

        // prologue: Q tile (128 rows) + key-tile pair 0 (tiles 0,1 -> bufs 0,1)
        {
            const __half* qp = qk + (size_t)(b * SEQ + q0) * 2048 + h * HD;
#pragma unroll
            for (int i = 0; i < 4; i++) {       // Q: 128 rows x 8 chunks = 1024
                const int c = t + i * 256;
                const int row = c >> 3, cc = c & 7;
                cp_async16(&Qs[row * AQS + cc * 4], qp + (size_t)row * 2048 + cc * 8);
            }
            load_kv(0, 0);
            load_kv(1, 1);
        }
        CP_COMMIT();
        CP_WAIT0();
        __syncthreads();

        // Q fragments -> registers, scaled by 0.125*log2(e) (base-2 softmax)
        unsigned qf[4][4];
        {
            const __half2 sc = __float2half2_rn(0.125f * 1.44269504f);
            const int r0 = (16 * w + gid) * AQS;
            const int r1 = (16 * w + gid + 8) * AQS;
#pragma unroll
            for (int s = 0; s < 4; s++) {
                unsigned u0 = Qs[r0 + 8 * s + tig];
                unsigned u1 = Qs[r1 + 8 * s + tig];
                unsigned u2 = Qs[r0 + 8 * s + tig + 4];
                unsigned u3 = Qs[r1 + 8 * s + tig + 4];
                __half2 h0 = __hmul2(*(__half2*)&u0, sc);
                __half2 h1 = __hmul2(*(__half2*)&u1, sc);
                __half2 h2 = __hmul2(*(__half2*)&u2, sc);
                __half2 h3 = __hmul2(*(__half2*)&u3, sc);
                qf[s][0] = *(unsigned*)&h0;
                qf[s][1] = *(unsigned*)&h1;
                qf[s][2] = *(unsigned*)&h2;
                qf[s][3] = *(unsigned*)&h3;
            }
        }

        float o[8][4];
#pragma unroll
        for (int j = 0; j < 8; j++)
#pragma unroll
            for (int e = 0; e < 4; e++) o[j][e] = 0.f;
        float m0 = -1e30f, m1 = -1e30f, l0 = 0.f, l1 = 0.f;

        const int row0    = q0 + 16 * w + gid;
        const int rowWmin = q0 + 16 * w;
        const int rowWmax = rowWmin + 15;
        const int npair   = qt + 1;

        for (int p = 0; p < npair; p++) {
            CP_WAIT0();
            __syncthreads();

            if (p + 1 < npair) {
                const int nb = 2 * ((p + 1) & 1);
                load_kv(nb,     2 * p + 2);
                load_kv(nb + 1, 2 * p + 3);
                CP_COMMIT();
            }

#pragma unroll
            for (int half = 0; half < 2; half++) {
                const int jt = 2 * p + half;
                const int k0 = jt * 64;
                if (k0 > rowWmax) continue;   // fully above diagonal: exact no-op

                const int buf = 2 * (p & 1) + half;
                const unsigned kBase = smb + (unsigned)(buf * AKS_ELEMS) * 4 + kLane;
                const unsigned vBase = smb + (unsigned)(4 * AKS_ELEMS + buf * AVS_ELEMS) * 4 + vLane;

                // S = Q K^T
                float sacc[8][4];
#pragma unroll
                for (int j = 0; j < 8; j++)
#pragma unroll
                    for (int e = 0; e < 4; e++) sacc[j][e] = 0.f;

#pragma unroll
                for (int s = 0; s < 4; s++) {
#pragma unroll
                    for (int pp = 0; pp < 4; pp++) {
                        unsigned k0r, k1r, k2r, k3r;
                        ldsm4(k0r, k1r, k2r, k3r, kBase + pp * (16 * AKS * 4) + s * 32);
                        mma_f16(sacc[2 * pp],     qf[s], k0r, k1r);
                        mma_f16(sacc[2 * pp + 1], qf[s], k2r, k3r);
                    }
                }

                // mask + row max
                const bool need_mask = (k0 + 63 > rowWmin);
                float mt0 = -1e30f, mt1 = -1e30f;
#pragma unroll
                for (int j = 0; j < 8; j++) {
                    const int cb = k0 + 8 * j + 2 * tig;
                    if (need_mask) {
                        if (cb     > row0)     sacc[j][0] = -1e30f;
                        if (cb + 1 > row0)     sacc[j][1] = -1e30f;
                        if (cb     > row0 + 8) sacc[j][2] = -1e30f;
                        if (cb + 1 > row0 + 8) sacc[j][3] = -1e30f;
                    }
                    mt0 = fmaxf(mt0, fmaxf(sacc[j][0], sacc[j][1]));
                    mt1 = fmaxf(mt1, fmaxf(sacc[j][2], sacc[j][3]));
                }
                mt0 = fmaxf(mt0, __shfl_xor_sync(0xffffffffu, mt0, 1));
                mt0 = fmaxf(mt0, __shfl_xor_sync(0xffffffffu, mt0, 2));
                mt1 = fmaxf(mt1, __shfl_xor_sync(0xffffffffu, mt1, 1));
                mt1 = fmaxf(mt1, __shfl_xor_sync(0xffffffffu, mt1, 2));

                const float mn0 = fmaxf(m0, mt0);
                const float mn1 = fmaxf(m1, mt1);
                const float al0 = fexp2(m0 - mn0);
                const float al1 = fexp2(m1 - mn1);
                m0 = mn0; m1 = mn1;

                // P = 2^(S - m): fp16 A-fragments in registers
                unsigned pf[4][4];
                float ls0 = 0.f, ls1 = 0.f;
#pragma unroll
                for (int j = 0; j < 8; j++) {
                    float p00 = fexp2(sacc[j][0] - mn0);
                    float p01 = fexp2(sacc[j][1] - mn0);
                    float p10 = fexp2(sacc[j][2] - mn1);
                    float p11 = fexp2(sacc[j][3] - mn1);
                    ls0 += p00 + p01;
                    ls1 += p10 + p11;
                    __half2 lo = __floats2half2_rn(p00, p01);
                    __half2 hi = __floats2half2_rn(p10, p11);
                    const int mm = j >> 1;
                    const int off = (j & 1) << 1;
                    pf[mm][off]     = *(unsigned*)&lo;
                    pf[mm][off + 1] = *(unsigned*)&hi;
                }
                ls0 += __shfl_xor_sync(0xffffffffu, ls0, 1);
                ls0 += __shfl_xor_sync(0xffffffffu, ls0, 2);
                ls1 += __shfl_xor_sync(0xffffffffu, ls1, 1);
                ls1 += __shfl_xor_sync(0xffffffffu, ls1, 2);
                l0 = l0 * al0 + ls0;
                l1 = l1 * al1 + ls1;

#pragma unroll
                for (int j = 0; j < 8; j++) {
                    o[j][0] *= al0; o[j][1] *= al0;
                    o[j][2] *= al1; o[j][3] *= al1;
                }

                // O += P V
#pragma unroll
                for (int mm = 0; mm < 4; mm++) {
#pragma unroll
                    for (int pp = 0; pp < 4; pp++) {
                        unsigned v0, v1, v2, v3;
                        ldsm4(v0, v1, v2, v3, vBase + pp * (16 * AVS * 4) + mm * 32);
                        mma_f16(o[2 * pp],     pf[mm], v0, v1);
                        mma_f16(o[2 * pp + 1], pf[mm], v2, v3);
                    }
                }
            }
        }

        // epilogue -> fp16 for the output projection
        const float i0 = 1.f / l0;
        const float i1 = 1.f / l1;
        __half2* op0 = (__half2*)(out + (size_t)(b * SEQ + row0) * D_MODEL + h * HD);
        __half2* op1 = (__half2*)(out + (size_t)(b * SEQ + row0 + 8) * D_MODEL + h * HD);
#pragma unroll
        for (int j = 0; j < 8; j++) {
            const int c = (8 * j + 2 * tig) >> 1;
            op0[c] = __floats2half2_rn(o[j][0] * i0, o[j][1] * i0);
            op1[c] = __floats2half2_rn(o[j][2] * i1, o[j][3] * i1);
        }
    }
}

extern "C" void kernel_launch(void* const* d_in, const int* in_sizes, int n_in,
                              void* d_out, int out_size) {
    const float* x     = (const float*)d_in[0];
    const float* w_qkv = (const float*)d_in[1];
    const float* w_o   = (const float*)d_in[2];
    float* out         = (float*)d_out;

    __half *qkh, *vt, *ao, *xh, *wqh, *woh;
    cudaGetSymbolAddress((void**)&qkh, g_qkh);
    cudaGetSymbolAddress((void**)&vt,  g_vt);
    cudaGetSymbolAddress((void**)&ao,  g_ao);
    cudaGetSymbolAddress((void**)&xh,  g_xh);
    cudaGetSymbolAddress((void**)&wqh, g_wqh);
    cudaGetSymbolAddress((void**)&woh, g_woh);

    static bool attr_set = false;
    if (!attr_set) {
        cudaFuncSetAttribute(gemm_h<0>, cudaFuncAttributeMaxDynamicSharedMemorySize, SMEM_GEMM);
        cudaFuncSetAttribute(gemm_h<1>, cudaFuncAttributeMaxDynamicSharedMemorySize, SMEM_GEMM);
        cudaFuncSetAttribute(attn_h, cudaFuncAttributeMaxDynamicSharedMemorySize, SMEM_ATTN);
        attr_set = true;
    }

    // 0) fp32 -> fp16 pre-pass
    conv_h<<<CONV_BLOCKS, 256>>>((const float4*)x, (const float4*)w_qkv, (const float4*)w_o,
                                 (uint2*)xh, (uint2*)wqh, (uint2*)woh);

    // 1) QKV projection (fp16 mma): Q|K -> fp16, V -> transposed fp16
    gemm_h<1><<<dim3(QKV_W / 128, M_TOT / 128), 256, SMEM_GEMM>>>(
        xh, wqh, qkh, vt, M_TOT, QKV_W, D_MODEL);

    // 2) causal attention -> fp16 (paired q-tiles: uniform work per block)
    attn_h<<<dim3(NQT / 2, NHEAD, BATCH), 256, SMEM_ATTN>>>(qkh, vt, ao);

    // 3) output projection (fp16 mma) -> fp32
    gemm_h<0><<<dim3(D_MODEL / 128, M_TOT / 128), 256, SMEM_GEMM>>>(
        ao, woh, out, nullptr, M_TOT, D_MODEL, D_MODEL);
}